// round 7
// baseline (speedup 1.0000x reference)
#include <cuda_runtime.h>
#include <cuda_bf16.h>
#include <cstdint>

#define Bb 8
#define Cc 1024
#define Tt 8
#define Ee 512
#define NN 6272
#define MM 1568
#define EPSV 1e-5f

typedef unsigned int u32;
typedef unsigned long long u64;
typedef __nv_bfloat16 bf16;

// ------------------- device scratch -------------------
__device__ bf16 g_xT_h[(long)Bb*NN*Cc], g_xT_l[(long)Bb*NN*Cc];     // x^T [B,N,C]
__device__ bf16 g_xsT_h[(long)Bb*MM*Cc], g_xsT_l[(long)Bb*MM*Cc];   // xsub^T [B,M,C]
__device__ bf16 g_th_h[(long)Bb*NN*Ee], g_th_l[(long)Bb*NN*Ee];     // theta^T [B,N,E]
__device__ bf16 g_ph_h[(long)Bb*MM*Ee], g_ph_l[(long)Bb*MM*Ee];     // phi^T [B,M,E]
__device__ bf16 g_g_h[(long)Bb*Ee*MM], g_g_l[(long)Bb*Ee*MM];       // g [B,E,M]
__device__ float g_sc[(long)Bb*NN*MM];                              // scores [B,N,M]
__device__ bf16 g_p_h[(long)Bb*NN*MM], g_p_l[(long)Bb*NN*MM];       // P [B,N,M]
__device__ bf16 g_y_h[(long)Bb*NN*Ee], g_y_l[(long)Bb*NN*Ee];       // y^T [B,N,E]
__device__ bf16 g_wth_h[Ee*Cc], g_wth_l[Ee*Cc];
__device__ bf16 g_wph_h[Ee*Cc], g_wph_l[Ee*Cc];
__device__ bf16 g_wg_h [Ee*Cc], g_wg_l [Ee*Cc];
__device__ bf16 g_wo_h [Cc*Ee], g_wo_l [Cc*Ee];
__device__ float g_scl[Cc], g_off[Cc];

// ------------------- helpers -------------------
__device__ __forceinline__ u32 s2u(const void* p){
    u32 a; asm("{ .reg .u64 t; cvta.to.shared.u64 t, %1; cvt.u32.u64 %0, t; }" : "=r"(a) : "l"(p)); return a;
}
__device__ __forceinline__ void cpa16(u32 dst, const void* src, int valid){
    int sz = valid ? 16 : 0;
    asm volatile("cp.async.cg.shared.global [%0], [%1], 16, %2;" :: "r"(dst), "l"(src), "r"(sz));
}
#define CP_COMMIT() asm volatile("cp.async.commit_group;" ::: "memory")
#define CP_WAIT1()  asm volatile("cp.async.wait_group 1;" ::: "memory")

__device__ __forceinline__ void ldm4(u32* r, u32 addr){
    asm volatile("ldmatrix.sync.aligned.m8n8.x4.shared.b16 {%0,%1,%2,%3}, [%4];"
        : "=r"(r[0]), "=r"(r[1]), "=r"(r[2]), "=r"(r[3]) : "r"(addr));
}
__device__ __forceinline__ void mma16816(float* c, const u32* a, const u32* b){
    asm volatile("mma.sync.aligned.m16n8k16.row.col.f32.bf16.bf16.f32 "
        "{%0,%1,%2,%3}, {%4,%5,%6,%7}, {%8,%9}, {%0,%1,%2,%3};"
        : "+f"(c[0]), "+f"(c[1]), "+f"(c[2]), "+f"(c[3])
        : "r"(a[0]), "r"(a[1]), "r"(a[2]), "r"(a[3]), "r"(b[0]), "r"(b[1]));
}

// smem geometry: rows padded to 80B (40 bf16) for conflict-free ldmatrix
#define LROW   80
#define TILEB  (128*LROW)      // 10240 B per 128x32 bf16 tile
#define STAGEB (4*TILEB)       // Ah, Al, Bh, Bl = 40960 B
#define NSTG   3
#define SMEMD  (NSTG*STAGEB)   // 122880 B

// ------------------- generic bf16-split warp-MMA GEMM -------------------
// C[z][o][n] = sum_k A[z][o][k] * B[z][n][k]   (both K-major, hi/lo split, 3 mma passes)
// OUTM: 0 fp32 out, 1 split bf16 hi/lo out
// BIASM: 0 none, 1 per-row bias[o], 2 per-col bias[n]
// BNM: 1 = v*scl[o]+off[o]+resid[z][o][n]
template<int OUTM, int BIASM, int BNM>
__global__ void __launch_bounds__(256, 1)
mma_gemm(const bf16* __restrict__ Ah, const bf16* __restrict__ Al, long sAz, int Arows,
         const bf16* __restrict__ Bh, const bf16* __restrict__ Bl, long sBz, int Brows,
         int K,
         float* __restrict__ Cf, bf16* __restrict__ Ch, bf16* __restrict__ Cl,
         long sCz, int ldC, int Crows, int Ccols,
         const float* __restrict__ bias, const float* __restrict__ scl,
         const float* __restrict__ off, const float* __restrict__ resid, long sRz)
{
    extern __shared__ char sm[];
    const int t   = threadIdx.x;
    const int wid = t >> 5, lid = t & 31;
    const int o0  = blockIdx.y * 128, n0 = blockIdx.x * 128;
    const int z   = blockIdx.z;
    const int wm  = wid & 3, wn = wid >> 2;   // warp tile 32x64

    const bf16* Ahz = Ah + (long)z * sAz;
    const bf16* Alz = Al + (long)z * sAz;
    const bf16* Bhz = Bh + (long)z * sBz;
    const bf16* Blz = Bl + (long)z * sBz;

    const u32 smb = s2u(sm);

    // per-thread cp.async indexing: 512 16B-chunks per 128x32 tile, 2 per thread
    const int id0 = t, id1 = t + 256;
    const int r0 = id0 >> 2, ch0 = id0 & 3;
    const int r1 = id1 >> 2, ch1 = id1 & 3;
    const int ar0 = o0 + r0, ar1 = o0 + r1;
    const int br0 = n0 + r0, br1 = n0 + r1;
    const int av0 = ar0 < Arows, av1 = ar1 < Arows;
    const int bv0 = br0 < Brows, bv1 = br1 < Brows;
    const long aoff0 = (long)(av0 ? ar0 : 0) * K + ch0 * 8;
    const long aoff1 = (long)(av1 ? ar1 : 0) * K + ch1 * 8;
    const long boff0 = (long)(bv0 ? br0 : 0) * K + ch0 * 8;
    const long boff1 = (long)(bv1 ? br1 : 0) * K + ch1 * 8;
    const u32 dst0 = (u32)(r0 * LROW + ch0 * 16);
    const u32 dst1 = (u32)(r1 * LROW + ch1 * 16);

    auto load_stage = [&](int st, int kb){
        u32 b = smb + st * STAGEB;
        long ko = (long)kb * 32;
        cpa16(b + dst0,             Ahz + aoff0 + ko, av0);
        cpa16(b + dst1,             Ahz + aoff1 + ko, av1);
        cpa16(b + TILEB   + dst0,   Alz + aoff0 + ko, av0);
        cpa16(b + TILEB   + dst1,   Alz + aoff1 + ko, av1);
        cpa16(b + 2*TILEB + dst0,   Bhz + boff0 + ko, bv0);
        cpa16(b + 2*TILEB + dst1,   Bhz + boff1 + ko, bv1);
        cpa16(b + 3*TILEB + dst0,   Blz + boff0 + ko, bv0);
        cpa16(b + 3*TILEB + dst1,   Blz + boff1 + ko, bv1);
        CP_COMMIT();
    };

    // ldmatrix lane offsets (relative to stage base); +ks*32 bytes per k16 step
    u32 aoffm[2], boffm[4];
#pragma unroll
    for (int i = 0; i < 2; i++)
        aoffm[i] = (u32)((wm*32 + i*16 + (lid & 15)) * LROW + (lid >> 4) * 16);
#pragma unroll
    for (int j = 0; j < 4; j++)
        boffm[j] = (u32)((wn*64 + j*16 + (lid & 7) + ((lid & 16) >> 1)) * LROW
                         + ((lid >> 3) & 1) * 16);

    float acc[2][8][4];
#pragma unroll
    for (int i = 0; i < 2; i++)
#pragma unroll
        for (int j = 0; j < 8; j++)
#pragma unroll
            for (int k = 0; k < 4; k++) acc[i][j][k] = 0.f;

    const int nkb = K >> 5;
    // prologue: fill stages 0 and 1
    load_stage(0, 0);
    load_stage(1, 1);

    int cur = 0;    // stage holding kb
    int nxt = 2;    // stage to fill with kb+2
    for (int kb = 0; kb < nkb; kb++){
        CP_WAIT1();          // stage `cur` (group kb) has landed
        __syncthreads();     // everyone done reading stage `nxt` (= stage of kb-1)
        if (kb + 2 < nkb) load_stage(nxt, kb + 2);
        else              CP_COMMIT();   // keep group pacing for wait_group 1

        const u32 base = smb + cur * STAGEB;
#pragma unroll
        for (int ks = 0; ks < 2; ks++){
            const u32 kofs = ks * 32;
            u32 ah[2][4], al[2][4], bh[4][4], bl[4][4];
            ldm4(ah[0], base + aoffm[0] + kofs);
            ldm4(ah[1], base + aoffm[1] + kofs);
            ldm4(al[0], base + TILEB + aoffm[0] + kofs);
            ldm4(al[1], base + TILEB + aoffm[1] + kofs);
#pragma unroll
            for (int j = 0; j < 4; j++) ldm4(bh[j], base + 2*TILEB + boffm[j] + kofs);
#pragma unroll
            for (int j = 0; j < 4; j++) ldm4(bl[j], base + 3*TILEB + boffm[j] + kofs);

            // pass-major: all 16 accs per pass -> no accumulator RAW chains
#pragma unroll
            for (int i = 0; i < 2; i++)
#pragma unroll
                for (int j8 = 0; j8 < 8; j8++)
                    mma16816(acc[i][j8], ah[i], &bh[j8 >> 1][(j8 & 1) * 2]);  // hi*hi
#pragma unroll
            for (int i = 0; i < 2; i++)
#pragma unroll
                for (int j8 = 0; j8 < 8; j8++)
                    mma16816(acc[i][j8], ah[i], &bl[j8 >> 1][(j8 & 1) * 2]);  // hi*lo
#pragma unroll
            for (int i = 0; i < 2; i++)
#pragma unroll
                for (int j8 = 0; j8 < 8; j8++)
                    mma16816(acc[i][j8], al[i], &bh[j8 >> 1][(j8 & 1) * 2]);  // lo*hi
        }
        cur = (cur == NSTG - 1) ? 0 : cur + 1;
        nxt = (nxt == NSTG - 1) ? 0 : nxt + 1;
    }

    // ------------------- epilogue -------------------
    const int q = lid >> 2, tq = lid & 3;
    const int rbase = o0 + wm * 32;
    const int cbase = n0 + wn * 64;
#pragma unroll
    for (int i = 0; i < 2; i++){
#pragma unroll
        for (int half = 0; half < 2; half++){
            const int row = rbase + i * 16 + q + half * 8;
            if (row >= Crows) continue;
            float brow = 0.f, sc_r = 0.f, of_r = 0.f;
            if (BIASM == 1) brow = bias[row];
            if (BNM == 1){ sc_r = scl[row]; of_r = off[row]; }
            const float* rrow = (BNM == 1) ? (resid + (long)z * sRz + (long)row * ldC) : nullptr;
            float* cfrow = (OUTM == 0) ? (Cf + (long)z * sCz + (long)row * ldC) : nullptr;
            bf16* chrow  = (OUTM == 1) ? (Ch + (long)z * sCz + (long)row * ldC) : nullptr;
            bf16* clrow  = (OUTM == 1) ? (Cl + (long)z * sCz + (long)row * ldC) : nullptr;
#pragma unroll
            for (int j8 = 0; j8 < 8; j8++){
                const int col = cbase + j8 * 8 + tq * 2;
                if (col >= Ccols) continue;
                float v0 = acc[i][j8][half * 2 + 0];
                float v1 = acc[i][j8][half * 2 + 1];
                if (BIASM == 1){ v0 += brow; v1 += brow; }
                if (BIASM == 2){ v0 += bias[col]; v1 += bias[col + 1]; }
                if (BNM == 1){
                    v0 = v0 * sc_r + of_r + rrow[col];
                    v1 = v1 * sc_r + of_r + rrow[col + 1];
                }
                if (OUTM == 0){
                    *(float2*)(cfrow + col) = make_float2(v0, v1);
                } else {
                    bf16 h0 = __float2bfloat16(v0);
                    bf16 h1 = __float2bfloat16(v1);
                    bf16 l0 = __float2bfloat16(v0 - __bfloat162float(h0));
                    bf16 l1 = __float2bfloat16(v1 - __bfloat162float(h1));
                    u32 hp = ((u32)__bfloat16_as_ushort(h1) << 16) | __bfloat16_as_ushort(h0);
                    u32 lp = ((u32)__bfloat16_as_ushort(l1) << 16) | __bfloat16_as_ushort(l0);
                    *(u32*)(chrow + col) = hp;
                    *(u32*)(clrow + col) = lp;
                }
            }
        }
    }
}

// ------------------- conversion kernels -------------------
// split all 4 weight matrices in one launch (each Ee*Cc = Cc*Ee elements)
__global__ void wsplit4(const float* __restrict__ w0, const float* __restrict__ w1,
                        const float* __restrict__ w2, const float* __restrict__ w3,
                        bf16* __restrict__ h0, bf16* __restrict__ l0,
                        bf16* __restrict__ h1, bf16* __restrict__ l1,
                        bf16* __restrict__ h2, bf16* __restrict__ l2,
                        bf16* __restrict__ h3, bf16* __restrict__ l3){
    const long n = (long)Ee * Cc;
    long i = (long)blockIdx.x * blockDim.x + threadIdx.x;
    if (i >= n) return;
    const float* in; bf16 *hi, *lo;
    switch (blockIdx.y){
        case 0: in = w0; hi = h0; lo = l0; break;
        case 1: in = w1; hi = h1; lo = l1; break;
        case 2: in = w2; hi = h2; lo = l2; break;
        default:in = w3; hi = h3; lo = l3; break;
    }
    float v = in[i];
    bf16 h = __float2bfloat16(v);
    hi[i] = h;
    lo[i] = __float2bfloat16(v - __bfloat162float(h));
}

// x [B,C,N] -> xT hi/lo [B,N,C]
__global__ void xpose_split(const float* __restrict__ x,
                            bf16* __restrict__ oh, bf16* __restrict__ ol){
    __shared__ float tile[32][33];
    const int tx = threadIdx.x, ty = threadIdx.y;
    const int n0 = blockIdx.x * 32, c0 = blockIdx.y * 32, z = blockIdx.z;
    const float* xz = x + (long)z * Cc * NN;
#pragma unroll
    for (int j = 0; j < 4; j++){
        int c = c0 + ty + j * 8;
        tile[ty + j * 8][tx] = xz[(long)c * NN + n0 + tx];
    }
    __syncthreads();
    bf16* ohz = oh + (long)z * NN * Cc;
    bf16* olz = ol + (long)z * NN * Cc;
#pragma unroll
    for (int j = 0; j < 4; j++){
        int n = n0 + ty + j * 8;
        float v = tile[tx][ty + j * 8];
        bf16 h = __float2bfloat16(v);
        long idx = (long)n * Cc + c0 + tx;
        ohz[idx] = h;
        olz[idx] = __float2bfloat16(v - __bfloat162float(h));
    }
}

// maxpool (1,2,2) + transpose + split: x [B,C,T,28,28] -> xsubT hi/lo [B,M,C]
__global__ void pool_xpose_split(const float* __restrict__ x,
                                 bf16* __restrict__ oh, bf16* __restrict__ ol){
    __shared__ float tile[32][33];
    const int tx = threadIdx.x, ty = threadIdx.y;
    const int m0 = blockIdx.x * 32, c0 = blockIdx.y * 32, z = blockIdx.z;
    const int m = m0 + tx;
    const int t_ = m / 196, r = m % 196, h2 = r / 14, w2 = r % 14;
#pragma unroll
    for (int j = 0; j < 4; j++){
        int c = c0 + ty + j * 8;
        const float* p = x + ((((long)z * Cc + c) * Tt + t_) * 28 + h2 * 2) * 28 + w2 * 2;
        float v = fmaxf(fmaxf(p[0], p[1]), fmaxf(p[28], p[29]));
        tile[ty + j * 8][tx] = v;
    }
    __syncthreads();
    bf16* ohz = oh + (long)z * MM * Cc;
    bf16* olz = ol + (long)z * MM * Cc;
#pragma unroll
    for (int j = 0; j < 4; j++){
        int mw = m0 + ty + j * 8;
        float v = tile[tx][ty + j * 8];
        bf16 h = __float2bfloat16(v);
        long idx = (long)mw * Cc + c0 + tx;
        ohz[idx] = h;
        olz[idx] = __float2bfloat16(v - __bfloat162float(h));
    }
}

// row softmax over 1568 keys -> split bf16 P
__global__ void softmax_split(const float* __restrict__ S,
                              bf16* __restrict__ ph, bf16* __restrict__ pl){
    const long row = blockIdx.x;
    const float* p = S + row * MM;
    const int t = threadIdx.x;
    float v[7];
    float lm = -3.4e38f;
#pragma unroll
    for (int it = 0; it < 7; it++){
        int idx = t + it * 256;
        v[it] = (idx < MM) ? p[idx] : -3.4e38f;
        lm = fmaxf(lm, v[it]);
    }
    __shared__ float red[256];
    red[t] = lm; __syncthreads();
    for (int s = 128; s > 0; s >>= 1){ if (t < s) red[t] = fmaxf(red[t], red[t + s]); __syncthreads(); }
    float m = red[0];
    __syncthreads();
    float ls = 0.f;
#pragma unroll
    for (int it = 0; it < 7; it++){
        int idx = t + it * 256;
        if (idx < MM){ float e = __expf(v[it] - m); v[it] = e; ls += e; }
    }
    red[t] = ls; __syncthreads();
    for (int s = 128; s > 0; s >>= 1){ if (t < s) red[t] += red[t + s]; __syncthreads(); }
    float inv = 1.f / red[0];
    bf16* phr = ph + row * MM;
    bf16* plr = pl + row * MM;
#pragma unroll
    for (int it = 0; it < 7; it++){
        int idx = t + it * 256;
        if (idx < MM){
            float val = v[it] * inv;
            bf16 h = __float2bfloat16(val);
            phr[idx] = h;
            plr[idx] = __float2bfloat16(val - __bfloat162float(h));
        }
    }
}

__global__ void affine_kernel(const float* __restrict__ bo, const float* __restrict__ gm,
                              const float* __restrict__ bt, const float* __restrict__ mn,
                              const float* __restrict__ vr,
                              float* __restrict__ scl, float* __restrict__ off){
    int c = blockIdx.x * blockDim.x + threadIdx.x;
    if (c < Cc){
        float s = gm[c] * rsqrtf(vr[c] + EPSV);
        scl[c] = s;
        off[c] = (bo[c] - mn[c]) * s + bt[c];
    }
}

// ------------------- launch -------------------
extern "C" void kernel_launch(void* const* d_in, const int* in_sizes, int n_in,
                              void* d_out, int out_size){
    const float* x       = (const float*)d_in[0];
    const float* w_theta = (const float*)d_in[1];
    const float* b_theta = (const float*)d_in[2];
    const float* w_phi   = (const float*)d_in[3];
    const float* b_phi   = (const float*)d_in[4];
    const float* w_g     = (const float*)d_in[5];
    const float* b_g     = (const float*)d_in[6];
    const float* w_out   = (const float*)d_in[7];
    const float* b_out   = (const float*)d_in[8];
    const float* bn_gm   = (const float*)d_in[9];
    const float* bn_bt   = (const float*)d_in[10];
    const float* bn_mn   = (const float*)d_in[11];
    const float* bn_vr   = (const float*)d_in[12];
    float* out = (float*)d_out;

    bf16 *xT_h, *xT_l, *xsT_h, *xsT_l, *th_h, *th_l, *ph_h, *ph_l;
    bf16 *gg_h, *gg_l, *p_h, *p_l, *y_h, *y_l;
    bf16 *wth_h, *wth_l, *wph_h, *wph_l, *wg_h, *wg_l, *wo_h, *wo_l;
    float *sc, *scl, *off;
    cudaGetSymbolAddress((void**)&xT_h, g_xT_h);  cudaGetSymbolAddress((void**)&xT_l, g_xT_l);
    cudaGetSymbolAddress((void**)&xsT_h, g_xsT_h);cudaGetSymbolAddress((void**)&xsT_l, g_xsT_l);
    cudaGetSymbolAddress((void**)&th_h, g_th_h);  cudaGetSymbolAddress((void**)&th_l, g_th_l);
    cudaGetSymbolAddress((void**)&ph_h, g_ph_h);  cudaGetSymbolAddress((void**)&ph_l, g_ph_l);
    cudaGetSymbolAddress((void**)&gg_h, g_g_h);   cudaGetSymbolAddress((void**)&gg_l, g_g_l);
    cudaGetSymbolAddress((void**)&sc, g_sc);
    cudaGetSymbolAddress((void**)&p_h, g_p_h);    cudaGetSymbolAddress((void**)&p_l, g_p_l);
    cudaGetSymbolAddress((void**)&y_h, g_y_h);    cudaGetSymbolAddress((void**)&y_l, g_y_l);
    cudaGetSymbolAddress((void**)&wth_h, g_wth_h);cudaGetSymbolAddress((void**)&wth_l, g_wth_l);
    cudaGetSymbolAddress((void**)&wph_h, g_wph_h);cudaGetSymbolAddress((void**)&wph_l, g_wph_l);
    cudaGetSymbolAddress((void**)&wg_h, g_wg_h);  cudaGetSymbolAddress((void**)&wg_l, g_wg_l);
    cudaGetSymbolAddress((void**)&wo_h, g_wo_h);  cudaGetSymbolAddress((void**)&wo_l, g_wo_l);
    cudaGetSymbolAddress((void**)&scl, g_scl);    cudaGetSymbolAddress((void**)&off, g_off);

    cudaFuncSetAttribute(mma_gemm<1,2,0>, cudaFuncAttributeMaxDynamicSharedMemorySize, SMEMD);
    cudaFuncSetAttribute(mma_gemm<1,1,0>, cudaFuncAttributeMaxDynamicSharedMemorySize, SMEMD);
    cudaFuncSetAttribute(mma_gemm<0,0,0>, cudaFuncAttributeMaxDynamicSharedMemorySize, SMEMD);
    cudaFuncSetAttribute(mma_gemm<1,0,0>, cudaFuncAttributeMaxDynamicSharedMemorySize, SMEMD);
    cudaFuncSetAttribute(mma_gemm<0,0,1>, cudaFuncAttributeMaxDynamicSharedMemorySize, SMEMD);

    // launch 0
    affine_kernel<<<(Cc + 255) / 256, 256>>>(b_out, bn_gm, bn_bt, bn_mn, bn_vr, scl, off);

    // launch 1: all 4 weight splits
    wsplit4<<<dim3((Ee * Cc + 255) / 256, 4), 256>>>(
        w_theta, w_phi, w_g, w_out,
        wth_h, wth_l, wph_h, wph_l, wg_h, wg_l, wo_h, wo_l);

    // launch 2
    xpose_split<<<dim3(NN / 32, Cc / 32, Bb), dim3(32, 8)>>>(x, xT_h, xT_l);

    // launch 3 (ncu capture lands here): thetaT[n,e] = sum_c xT[n,c] w_theta[e,c] + b_theta[e]
    mma_gemm<1,2,0><<<dim3(Ee / 128, NN / 128, Bb), 256, SMEMD>>>(
        xT_h, xT_l, (long)NN * Cc, NN,
        wth_h, wth_l, 0L, Ee, Cc,
        nullptr, th_h, th_l, (long)NN * Ee, Ee, NN, Ee,
        b_theta, nullptr, nullptr, nullptr, 0L);

    // launch 4
    pool_xpose_split<<<dim3(MM / 32, Cc / 32, Bb), dim3(32, 8)>>>(x, xsT_h, xsT_l);

    // launch 5: phiT[m,e] = sum_c xsT[m,c] w_phi[e,c] + b_phi[e]
    mma_gemm<1,2,0><<<dim3(Ee / 128, (MM + 127) / 128, Bb), 256, SMEMD>>>(
        xsT_h, xsT_l, (long)MM * Cc, MM,
        wph_h, wph_l, 0L, Ee, Cc,
        nullptr, ph_h, ph_l, (long)MM * Ee, Ee, MM, Ee,
        b_phi, nullptr, nullptr, nullptr, 0L);

    // launch 6: g[e,m] = sum_c w_g[e,c] xsT[m,c] + b_g[e]
    mma_gemm<1,1,0><<<dim3((MM + 127) / 128, Ee / 128, Bb), 256, SMEMD>>>(
        wg_h, wg_l, 0L, Ee,
        xsT_h, xsT_l, (long)MM * Cc, MM, Cc,
        nullptr, gg_h, gg_l, (long)Ee * MM, MM, Ee, MM,
        b_g, nullptr, nullptr, nullptr, 0L);

    // launch 7: scores[n,m] = sum_e thetaT[n,e] phiT[m,e]
    mma_gemm<0,0,0><<<dim3((MM + 127) / 128, NN / 128, Bb), 256, SMEMD>>>(
        th_h, th_l, (long)NN * Ee, NN,
        ph_h, ph_l, (long)MM * Ee, MM, Ee,
        sc, nullptr, nullptr, (long)NN * MM, MM, NN, MM,
        nullptr, nullptr, nullptr, nullptr, 0L);

    // launch 8
    softmax_split<<<Bb * NN, 256>>>(sc, p_h, p_l);

    // launch 9: yT[n,e] = sum_m P[n,m] g[e,m]
    mma_gemm<1,0,0><<<dim3(Ee / 128, NN / 128, Bb), 256, SMEMD>>>(
        p_h, p_l, (long)NN * MM, NN,
        gg_h, gg_l, (long)Ee * MM, Ee, MM,
        nullptr, y_h, y_l, (long)NN * Ee, Ee, NN, Ee,
        nullptr, nullptr, nullptr, nullptr, 0L);

    // launch 10: out[c,n] = BN(sum_e w_out[c,e] yT[n,e]) + x[c,n]
    mma_gemm<0,0,1><<<dim3(NN / 128, Cc / 128, Bb), 256, SMEMD>>>(
        wo_h, wo_l, 0L, Cc,
        y_h, y_l, (long)NN * Ee, NN, Ee,
        out, nullptr, nullptr, (long)Cc * NN, NN, Cc, NN,
        nullptr, scl, off, x, (long)Cc * NN);
}

// round 9
// speedup vs baseline: 1.7462x; 1.7462x over previous
#include <cuda_runtime.h>
#include <cuda_bf16.h>
#include <cstdint>

#define Bb 8
#define Cc 1024
#define Tt 8
#define Ee 512
#define NN 6272
#define MM 1568
#define EPSV 1e-5f

typedef unsigned int u32;
typedef unsigned long long u64;
typedef __nv_bfloat16 bf16;

// ------------------- device scratch -------------------
__device__ bf16 g_xT_h[(long)Bb*NN*Cc], g_xT_l[(long)Bb*NN*Cc];     // x^T [B,N,C]
__device__ bf16 g_xsT_h[(long)Bb*MM*Cc], g_xsT_l[(long)Bb*MM*Cc];   // xsub^T [B,M,C]
__device__ bf16 g_th_h[(long)Bb*NN*Ee], g_th_l[(long)Bb*NN*Ee];     // theta^T [B,N,E]
__device__ bf16 g_ph_h[(long)Bb*MM*Ee], g_ph_l[(long)Bb*MM*Ee];     // phi^T [B,M,E]
__device__ bf16 g_g_h[(long)Bb*Ee*MM], g_g_l[(long)Bb*Ee*MM];       // g [B,E,M]
__device__ float g_sc[(long)Bb*NN*MM];                              // scores [B,N,M]
__device__ bf16 g_p_h[(long)Bb*NN*MM], g_p_l[(long)Bb*NN*MM];       // P [B,N,M]
__device__ bf16 g_y_h[(long)Bb*NN*Ee], g_y_l[(long)Bb*NN*Ee];       // y^T [B,N,E]
__device__ bf16 g_wth_h[Ee*Cc], g_wth_l[Ee*Cc];
__device__ bf16 g_wph_h[Ee*Cc], g_wph_l[Ee*Cc];
__device__ bf16 g_wg_h [Ee*Cc], g_wg_l [Ee*Cc];
__device__ bf16 g_wo_h [Cc*Ee], g_wo_l [Cc*Ee];
__device__ float g_scl[Cc], g_off[Cc];

// ------------------- helpers -------------------
__device__ __forceinline__ u32 s2u(const void* p){
    u32 a; asm("{ .reg .u64 t; cvta.to.shared.u64 t, %1; cvt.u32.u64 %0, t; }" : "=r"(a) : "l"(p)); return a;
}
__device__ __forceinline__ void cpa16(u32 dst, const void* src, int valid){
    int sz = valid ? 16 : 0;
    asm volatile("cp.async.cg.shared.global [%0], [%1], 16, %2;" :: "r"(dst), "l"(src), "r"(sz));
}
#define CP_COMMIT() asm volatile("cp.async.commit_group;" ::: "memory")
#define CP_WAIT1()  asm volatile("cp.async.wait_group 1;" ::: "memory")

__device__ __forceinline__ void ldm4(u32* r, u32 addr){
    asm volatile("ldmatrix.sync.aligned.m8n8.x4.shared.b16 {%0,%1,%2,%3}, [%4];"
        : "=r"(r[0]), "=r"(r[1]), "=r"(r[2]), "=r"(r[3]) : "r"(addr));
}
__device__ __forceinline__ void mma16816(float* c, const u32* a, const u32* b){
    asm volatile("mma.sync.aligned.m16n8k16.row.col.f32.bf16.bf16.f32 "
        "{%0,%1,%2,%3}, {%4,%5,%6,%7}, {%8,%9}, {%0,%1,%2,%3};"
        : "+f"(c[0]), "+f"(c[1]), "+f"(c[2]), "+f"(c[3])
        : "r"(a[0]), "r"(a[1]), "r"(a[2]), "r"(a[3]), "r"(b[0]), "r"(b[1]));
}

// smem geometry: rows padded to 80B (40 bf16) for conflict-free ldmatrix
#define LROW   80
#define TILEB  (128*LROW)      // 10240 B per 128x32 bf16 tile
#define STAGEB (4*TILEB)       // Ah, Al, Bh, Bl = 40960 B
#define NSTG   2
#define SMEMD  (NSTG*STAGEB)   // 81920 B -> 2 CTAs / SM

// ------------------- generic bf16-split warp-MMA GEMM -------------------
// C[z][o][n] = sum_k A[z][o][k] * B[z][n][k]   (both K-major, hi/lo split, 3 mma passes)
// OUTM: 0 fp32 out, 1 split bf16 hi/lo out
// BIASM: 0 none, 1 per-row bias[o], 2 per-col bias[n]
// BNM: 1 = v*scl[o]+off[o]+resid[z][o][n]
template<int OUTM, int BIASM, int BNM>
__global__ void __launch_bounds__(256, 2)
mma_gemm(const bf16* __restrict__ Ah, const bf16* __restrict__ Al, long sAz, int Arows,
         const bf16* __restrict__ Bh, const bf16* __restrict__ Bl, long sBz, int Brows,
         int K,
         float* __restrict__ Cf, bf16* __restrict__ Ch, bf16* __restrict__ Cl,
         long sCz, int ldC, int Crows, int Ccols,
         const float* __restrict__ bias, const float* __restrict__ scl,
         const float* __restrict__ off, const float* __restrict__ resid, long sRz)
{
    extern __shared__ char sm[];
    const int t   = threadIdx.x;
    const int wid = t >> 5, lid = t & 31;
    const int o0  = blockIdx.y * 128, n0 = blockIdx.x * 128;
    const int z   = blockIdx.z;
    const int wm  = wid & 3, wn = wid >> 2;   // warp tile 32x64

    const bf16* Ahz = Ah + (long)z * sAz;
    const bf16* Alz = Al + (long)z * sAz;
    const bf16* Bhz = Bh + (long)z * sBz;
    const bf16* Blz = Bl + (long)z * sBz;

    const u32 smb = s2u(sm);

    // per-thread cp.async indexing: 512 16B-chunks per 128x32 tile, 2 per thread
    const int id0 = t, id1 = t + 256;
    const int r0 = id0 >> 2, ch0 = id0 & 3;
    const int r1 = id1 >> 2, ch1 = id1 & 3;
    const int ar0 = o0 + r0, ar1 = o0 + r1;
    const int br0 = n0 + r0, br1 = n0 + r1;
    const int av0 = ar0 < Arows, av1 = ar1 < Arows;
    const int bv0 = br0 < Brows, bv1 = br1 < Brows;
    const long aoff0 = (long)(av0 ? ar0 : 0) * K + ch0 * 8;
    const long aoff1 = (long)(av1 ? ar1 : 0) * K + ch1 * 8;
    const long boff0 = (long)(bv0 ? br0 : 0) * K + ch0 * 8;
    const long boff1 = (long)(bv1 ? br1 : 0) * K + ch1 * 8;
    const u32 dst0 = (u32)(r0 * LROW + ch0 * 16);
    const u32 dst1 = (u32)(r1 * LROW + ch1 * 16);

    auto load_stage = [&](int st, int kb){
        u32 b = smb + st * STAGEB;
        long ko = (long)kb * 32;
        cpa16(b + dst0,             Ahz + aoff0 + ko, av0);
        cpa16(b + dst1,             Ahz + aoff1 + ko, av1);
        cpa16(b + TILEB   + dst0,   Alz + aoff0 + ko, av0);
        cpa16(b + TILEB   + dst1,   Alz + aoff1 + ko, av1);
        cpa16(b + 2*TILEB + dst0,   Bhz + boff0 + ko, bv0);
        cpa16(b + 2*TILEB + dst1,   Bhz + boff1 + ko, bv1);
        cpa16(b + 3*TILEB + dst0,   Blz + boff0 + ko, bv0);
        cpa16(b + 3*TILEB + dst1,   Blz + boff1 + ko, bv1);
        CP_COMMIT();
    };

    // ldmatrix lane offsets (relative to stage base); +ks*32 bytes per k16 step
    u32 aoffm[2], boffm[4];
#pragma unroll
    for (int i = 0; i < 2; i++)
        aoffm[i] = (u32)((wm*32 + i*16 + (lid & 15)) * LROW + (lid >> 4) * 16);
#pragma unroll
    for (int j = 0; j < 4; j++)
        boffm[j] = (u32)((wn*64 + j*16 + (lid & 7) + ((lid & 16) >> 1)) * LROW
                         + ((lid >> 3) & 1) * 16);

    float acc[2][8][4];
#pragma unroll
    for (int i = 0; i < 2; i++)
#pragma unroll
        for (int j = 0; j < 8; j++)
#pragma unroll
            for (int k = 0; k < 4; k++) acc[i][j][k] = 0.f;

    const int nkb = K >> 5;
    // prologue: fill both stages
    load_stage(0, 0);
    load_stage(1, 1);

    for (int kb = 0; kb < nkb; kb++){
        CP_WAIT1();          // group kb landed (<=1 group still in flight)
        __syncthreads();

        const u32 base = smb + (kb & 1) * STAGEB;
#pragma unroll
        for (int ks = 0; ks < 2; ks++){
            const u32 kofs = ks * 32;
            u32 ah[2][4], al[2][4], bh[4][4], bl[4][4];
            ldm4(ah[0], base + aoffm[0] + kofs);
            ldm4(ah[1], base + aoffm[1] + kofs);
            ldm4(al[0], base + TILEB + aoffm[0] + kofs);
            ldm4(al[1], base + TILEB + aoffm[1] + kofs);
#pragma unroll
            for (int j = 0; j < 4; j++) ldm4(bh[j], base + 2*TILEB + boffm[j] + kofs);
#pragma unroll
            for (int j = 0; j < 4; j++) ldm4(bl[j], base + 3*TILEB + boffm[j] + kofs);
#pragma unroll
            for (int i = 0; i < 2; i++){
#pragma unroll
                for (int j8 = 0; j8 < 8; j8++){
                    const u32* bhp = &bh[j8 >> 1][(j8 & 1) * 2];
                    const u32* blp = &bl[j8 >> 1][(j8 & 1) * 2];
                    mma16816(acc[i][j8], ah[i], bhp);   // hi*hi
                    mma16816(acc[i][j8], ah[i], blp);   // hi*lo
                    mma16816(acc[i][j8], al[i], bhp);   // lo*hi
                }
            }
        }

        __syncthreads();     // all warps done reading stage (kb&1)
        if (kb + 2 < nkb) load_stage(kb & 1, kb + 2);
        else              CP_COMMIT();   // empty group keeps wait_group 1 pacing
    }

    // ------------------- epilogue -------------------
    const int q = lid >> 2, tq = lid & 3;
    const int rbase = o0 + wm * 32;
    const int cbase = n0 + wn * 64;
#pragma unroll
    for (int i = 0; i < 2; i++){
#pragma unroll
        for (int half = 0; half < 2; half++){
            const int row = rbase + i * 16 + q + half * 8;
            if (row >= Crows) continue;
            float brow = 0.f, sc_r = 0.f, of_r = 0.f;
            if (BIASM == 1) brow = bias[row];
            if (BNM == 1){ sc_r = scl[row]; of_r = off[row]; }
            const float* rrow = (BNM == 1) ? (resid + (long)z * sRz + (long)row * ldC) : nullptr;
            float* cfrow = (OUTM == 0) ? (Cf + (long)z * sCz + (long)row * ldC) : nullptr;
            bf16* chrow  = (OUTM == 1) ? (Ch + (long)z * sCz + (long)row * ldC) : nullptr;
            bf16* clrow  = (OUTM == 1) ? (Cl + (long)z * sCz + (long)row * ldC) : nullptr;
#pragma unroll
            for (int j8 = 0; j8 < 8; j8++){
                const int col = cbase + j8 * 8 + tq * 2;
                if (col >= Ccols) continue;
                float v0 = acc[i][j8][half * 2 + 0];
                float v1 = acc[i][j8][half * 2 + 1];
                if (BIASM == 1){ v0 += brow; v1 += brow; }
                if (BIASM == 2){ v0 += bias[col]; v1 += bias[col + 1]; }
                if (BNM == 1){
                    v0 = v0 * sc_r + of_r + rrow[col];
                    v1 = v1 * sc_r + of_r + rrow[col + 1];
                }
                if (OUTM == 0){
                    *(float2*)(cfrow + col) = make_float2(v0, v1);
                } else {
                    bf16 h0 = __float2bfloat16(v0);
                    bf16 h1 = __float2bfloat16(v1);
                    bf16 l0 = __float2bfloat16(v0 - __bfloat162float(h0));
                    bf16 l1 = __float2bfloat16(v1 - __bfloat162float(h1));
                    u32 hp = ((u32)__bfloat16_as_ushort(h1) << 16) | __bfloat16_as_ushort(h0);
                    u32 lp = ((u32)__bfloat16_as_ushort(l1) << 16) | __bfloat16_as_ushort(l0);
                    *(u32*)(chrow + col) = hp;
                    *(u32*)(clrow + col) = lp;
                }
            }
        }
    }
}

// ------------------- conversion kernels -------------------
// split all 4 weight matrices in one launch (each Ee*Cc = Cc*Ee elements)
__global__ void wsplit4(const float* __restrict__ w0, const float* __restrict__ w1,
                        const float* __restrict__ w2, const float* __restrict__ w3,
                        bf16* __restrict__ h0, bf16* __restrict__ l0,
                        bf16* __restrict__ h1, bf16* __restrict__ l1,
                        bf16* __restrict__ h2, bf16* __restrict__ l2,
                        bf16* __restrict__ h3, bf16* __restrict__ l3){
    const long n = (long)Ee * Cc;
    long i = (long)blockIdx.x * blockDim.x + threadIdx.x;
    if (i >= n) return;
    const float* in; bf16 *hi, *lo;
    switch (blockIdx.y){
        case 0: in = w0; hi = h0; lo = l0; break;
        case 1: in = w1; hi = h1; lo = l1; break;
        case 2: in = w2; hi = h2; lo = l2; break;
        default:in = w3; hi = h3; lo = l3; break;
    }
    float v = in[i];
    bf16 h = __float2bfloat16(v);
    hi[i] = h;
    lo[i] = __float2bfloat16(v - __bfloat162float(h));
}

// x [B,C,N] -> xT hi/lo [B,N,C]
__global__ void xpose_split(const float* __restrict__ x,
                            bf16* __restrict__ oh, bf16* __restrict__ ol){
    __shared__ float tile[32][33];
    const int tx = threadIdx.x, ty = threadIdx.y;
    const int n0 = blockIdx.x * 32, c0 = blockIdx.y * 32, z = blockIdx.z;
    const float* xz = x + (long)z * Cc * NN;
#pragma unroll
    for (int j = 0; j < 4; j++){
        int c = c0 + ty + j * 8;
        tile[ty + j * 8][tx] = xz[(long)c * NN + n0 + tx];
    }
    __syncthreads();
    bf16* ohz = oh + (long)z * NN * Cc;
    bf16* olz = ol + (long)z * NN * Cc;
#pragma unroll
    for (int j = 0; j < 4; j++){
        int n = n0 + ty + j * 8;
        float v = tile[tx][ty + j * 8];
        bf16 h = __float2bfloat16(v);
        long idx = (long)n * Cc + c0 + tx;
        ohz[idx] = h;
        olz[idx] = __float2bfloat16(v - __bfloat162float(h));
    }
}

// maxpool (1,2,2) + transpose + split: x [B,C,T,28,28] -> xsubT hi/lo [B,M,C]
__global__ void pool_xpose_split(const float* __restrict__ x,
                                 bf16* __restrict__ oh, bf16* __restrict__ ol){
    __shared__ float tile[32][33];
    const int tx = threadIdx.x, ty = threadIdx.y;
    const int m0 = blockIdx.x * 32, c0 = blockIdx.y * 32, z = blockIdx.z;
    const int m = m0 + tx;
    const int t_ = m / 196, r = m % 196, h2 = r / 14, w2 = r % 14;
#pragma unroll
    for (int j = 0; j < 4; j++){
        int c = c0 + ty + j * 8;
        const float* p = x + ((((long)z * Cc + c) * Tt + t_) * 28 + h2 * 2) * 28 + w2 * 2;
        float v = fmaxf(fmaxf(p[0], p[1]), fmaxf(p[28], p[29]));
        tile[ty + j * 8][tx] = v;
    }
    __syncthreads();
    bf16* ohz = oh + (long)z * MM * Cc;
    bf16* olz = ol + (long)z * MM * Cc;
#pragma unroll
    for (int j = 0; j < 4; j++){
        int mw = m0 + ty + j * 8;
        float v = tile[tx][ty + j * 8];
        bf16 h = __float2bfloat16(v);
        long idx = (long)mw * Cc + c0 + tx;
        ohz[idx] = h;
        olz[idx] = __float2bfloat16(v - __bfloat162float(h));
    }
}

// row softmax over 1568 keys -> split bf16 P
__global__ void softmax_split(const float* __restrict__ S,
                              bf16* __restrict__ ph, bf16* __restrict__ pl){
    const long row = blockIdx.x;
    const float* p = S + row * MM;
    const int t = threadIdx.x;
    float v[7];
    float lm = -3.4e38f;
#pragma unroll
    for (int it = 0; it < 7; it++){
        int idx = t + it * 256;
        v[it] = (idx < MM) ? p[idx] : -3.4e38f;
        lm = fmaxf(lm, v[it]);
    }
    __shared__ float red[256];
    red[t] = lm; __syncthreads();
    for (int s = 128; s > 0; s >>= 1){ if (t < s) red[t] = fmaxf(red[t], red[t + s]); __syncthreads(); }
    float m = red[0];
    __syncthreads();
    float ls = 0.f;
#pragma unroll
    for (int it = 0; it < 7; it++){
        int idx = t + it * 256;
        if (idx < MM){ float e = __expf(v[it] - m); v[it] = e; ls += e; }
    }
    red[t] = ls; __syncthreads();
    for (int s = 128; s > 0; s >>= 1){ if (t < s) red[t] += red[t + s]; __syncthreads(); }
    float inv = 1.f / red[0];
    bf16* phr = ph + row * MM;
    bf16* plr = pl + row * MM;
#pragma unroll
    for (int it = 0; it < 7; it++){
        int idx = t + it * 256;
        if (idx < MM){
            float val = v[it] * inv;
            bf16 h = __float2bfloat16(val);
            phr[idx] = h;
            plr[idx] = __float2bfloat16(val - __bfloat162float(h));
        }
    }
}

__global__ void affine_kernel(const float* __restrict__ bo, const float* __restrict__ gm,
                              const float* __restrict__ bt, const float* __restrict__ mn,
                              const float* __restrict__ vr,
                              float* __restrict__ scl, float* __restrict__ off){
    int c = blockIdx.x * blockDim.x + threadIdx.x;
    if (c < Cc){
        float s = gm[c] * rsqrtf(vr[c] + EPSV);
        scl[c] = s;
        off[c] = (bo[c] - mn[c]) * s + bt[c];
    }
}

// ------------------- launch -------------------
extern "C" void kernel_launch(void* const* d_in, const int* in_sizes, int n_in,
                              void* d_out, int out_size){
    const float* x       = (const float*)d_in[0];
    const float* w_theta = (const float*)d_in[1];
    const float* b_theta = (const float*)d_in[2];
    const float* w_phi   = (const float*)d_in[3];
    const float* b_phi   = (const float*)d_in[4];
    const float* w_g     = (const float*)d_in[5];
    const float* b_g     = (const float*)d_in[6];
    const float* w_out   = (const float*)d_in[7];
    const float* b_out   = (const float*)d_in[8];
    const float* bn_gm   = (const float*)d_in[9];
    const float* bn_bt   = (const float*)d_in[10];
    const float* bn_mn   = (const float*)d_in[11];
    const float* bn_vr   = (const float*)d_in[12];
    float* out = (float*)d_out;

    bf16 *xT_h, *xT_l, *xsT_h, *xsT_l, *th_h, *th_l, *ph_h, *ph_l;
    bf16 *gg_h, *gg_l, *p_h, *p_l, *y_h, *y_l;
    bf16 *wth_h, *wth_l, *wph_h, *wph_l, *wg_h, *wg_l, *wo_h, *wo_l;
    float *sc, *scl, *off;
    cudaGetSymbolAddress((void**)&xT_h, g_xT_h);  cudaGetSymbolAddress((void**)&xT_l, g_xT_l);
    cudaGetSymbolAddress((void**)&xsT_h, g_xsT_h);cudaGetSymbolAddress((void**)&xsT_l, g_xsT_l);
    cudaGetSymbolAddress((void**)&th_h, g_th_h);  cudaGetSymbolAddress((void**)&th_l, g_th_l);
    cudaGetSymbolAddress((void**)&ph_h, g_ph_h);  cudaGetSymbolAddress((void**)&ph_l, g_ph_l);
    cudaGetSymbolAddress((void**)&gg_h, g_g_h);   cudaGetSymbolAddress((void**)&gg_l, g_g_l);
    cudaGetSymbolAddress((void**)&sc, g_sc);
    cudaGetSymbolAddress((void**)&p_h, g_p_h);    cudaGetSymbolAddress((void**)&p_l, g_p_l);
    cudaGetSymbolAddress((void**)&y_h, g_y_h);    cudaGetSymbolAddress((void**)&y_l, g_y_l);
    cudaGetSymbolAddress((void**)&wth_h, g_wth_h);cudaGetSymbolAddress((void**)&wth_l, g_wth_l);
    cudaGetSymbolAddress((void**)&wph_h, g_wph_h);cudaGetSymbolAddress((void**)&wph_l, g_wph_l);
    cudaGetSymbolAddress((void**)&wg_h, g_wg_h);  cudaGetSymbolAddress((void**)&wg_l, g_wg_l);
    cudaGetSymbolAddress((void**)&wo_h, g_wo_h);  cudaGetSymbolAddress((void**)&wo_l, g_wo_l);
    cudaGetSymbolAddress((void**)&scl, g_scl);    cudaGetSymbolAddress((void**)&off, g_off);

    cudaFuncSetAttribute(mma_gemm<1,2,0>, cudaFuncAttributeMaxDynamicSharedMemorySize, SMEMD);
    cudaFuncSetAttribute(mma_gemm<1,1,0>, cudaFuncAttributeMaxDynamicSharedMemorySize, SMEMD);
    cudaFuncSetAttribute(mma_gemm<0,0,0>, cudaFuncAttributeMaxDynamicSharedMemorySize, SMEMD);
    cudaFuncSetAttribute(mma_gemm<1,0,0>, cudaFuncAttributeMaxDynamicSharedMemorySize, SMEMD);
    cudaFuncSetAttribute(mma_gemm<0,0,1>, cudaFuncAttributeMaxDynamicSharedMemorySize, SMEMD);

    // launch 0
    affine_kernel<<<(Cc + 255) / 256, 256>>>(b_out, bn_gm, bn_bt, bn_mn, bn_vr, scl, off);

    // launch 1: all 4 weight splits
    wsplit4<<<dim3((Ee * Cc + 255) / 256, 4), 256>>>(
        w_theta, w_phi, w_g, w_out,
        wth_h, wth_l, wph_h, wph_l, wg_h, wg_l, wo_h, wo_l);

    // launch 2
    xpose_split<<<dim3(NN / 32, Cc / 32, Bb), dim3(32, 8)>>>(x, xT_h, xT_l);

    // launch 3 (ncu capture lands here): thetaT[n,e] = sum_c xT[n,c] w_theta[e,c] + b_theta[e]
    mma_gemm<1,2,0><<<dim3(Ee / 128, NN / 128, Bb), 256, SMEMD>>>(
        xT_h, xT_l, (long)NN * Cc, NN,
        wth_h, wth_l, 0L, Ee, Cc,
        nullptr, th_h, th_l, (long)NN * Ee, Ee, NN, Ee,
        b_theta, nullptr, nullptr, nullptr, 0L);

    // launch 4
    pool_xpose_split<<<dim3(MM / 32, Cc / 32, Bb), dim3(32, 8)>>>(x, xsT_h, xsT_l);

    // launch 5: phiT[m,e] = sum_c xsT[m,c] w_phi[e,c] + b_phi[e]
    mma_gemm<1,2,0><<<dim3(Ee / 128, (MM + 127) / 128, Bb), 256, SMEMD>>>(
        xsT_h, xsT_l, (long)MM * Cc, MM,
        wph_h, wph_l, 0L, Ee, Cc,
        nullptr, ph_h, ph_l, (long)MM * Ee, Ee, MM, Ee,
        b_phi, nullptr, nullptr, nullptr, 0L);

    // launch 6: g[e,m] = sum_c w_g[e,c] xsT[m,c] + b_g[e]
    mma_gemm<1,1,0><<<dim3((MM + 127) / 128, Ee / 128, Bb), 256, SMEMD>>>(
        wg_h, wg_l, 0L, Ee,
        xsT_h, xsT_l, (long)MM * Cc, MM, Cc,
        nullptr, gg_h, gg_l, (long)Ee * MM, MM, Ee, MM,
        b_g, nullptr, nullptr, nullptr, 0L);

    // launch 7: scores[n,m] = sum_e thetaT[n,e] phiT[m,e]
    mma_gemm<0,0,0><<<dim3((MM + 127) / 128, NN / 128, Bb), 256, SMEMD>>>(
        th_h, th_l, (long)NN * Ee, NN,
        ph_h, ph_l, (long)MM * Ee, MM, Ee,
        sc, nullptr, nullptr, (long)NN * MM, MM, NN, MM,
        nullptr, nullptr, nullptr, nullptr, 0L);

    // launch 8
    softmax_split<<<Bb * NN, 256>>>(sc, p_h, p_l);

    // launch 9: yT[n,e] = sum_m P[n,m] g[e,m]
    mma_gemm<1,0,0><<<dim3(Ee / 128, NN / 128, Bb), 256, SMEMD>>>(
        p_h, p_l, (long)NN * MM, NN,
        gg_h, gg_l, (long)Ee * MM, Ee, MM,
        nullptr, y_h, y_l, (long)NN * Ee, Ee, NN, Ee,
        nullptr, nullptr, nullptr, nullptr, 0L);

    // launch 10: out[c,n] = BN(sum_e w_out[c,e] yT[n,e]) + x[c,n]
    mma_gemm<0,0,1><<<dim3(NN / 128, Cc / 128, Bb), 256, SMEMD>>>(
        wo_h, wo_l, 0L, Cc,
        y_h, y_l, (long)NN * Ee, NN, Ee,
        out, nullptr, nullptr, (long)Cc * NN, NN, Cc, NN,
        nullptr, scl, off, x, (long)Cc * NN);
}

// round 11
// speedup vs baseline: 2.1001x; 1.2026x over previous
#include <cuda_runtime.h>
#include <cuda_bf16.h>
#include <cstdint>

#define Bb 8
#define Cc 1024
#define Tt 8
#define Ee 512
#define NN 6272
#define MM 1568
#define EPSV 1e-5f

typedef unsigned int u32;
typedef unsigned long long u64;
typedef __nv_bfloat16 bf16;

// ------------------- device scratch -------------------
__device__ bf16 g_xT_h[(long)Bb*NN*Cc], g_xT_l[(long)Bb*NN*Cc];     // x^T [B,N,C]
__device__ bf16 g_xsT_h[(long)Bb*MM*Cc], g_xsT_l[(long)Bb*MM*Cc];   // xsub^T [B,M,C]
__device__ bf16 g_th_h[(long)Bb*NN*Ee], g_th_l[(long)Bb*NN*Ee];     // theta^T [B,N,E]
__device__ bf16 g_ph_h[(long)Bb*MM*Ee], g_ph_l[(long)Bb*MM*Ee];     // phi^T [B,M,E]
__device__ bf16 g_g_h[(long)Bb*Ee*MM], g_g_l[(long)Bb*Ee*MM];       // g [B,E,M]
__device__ float g_sc[(long)Bb*NN*MM];                              // scores [B,N,M]
__device__ bf16 g_p_h[(long)Bb*NN*MM], g_p_l[(long)Bb*NN*MM];       // P [B,N,M]
__device__ bf16 g_y_h[(long)Bb*NN*Ee], g_y_l[(long)Bb*NN*Ee];       // y^T [B,N,E]
__device__ bf16 g_wth_h[Ee*Cc], g_wth_l[Ee*Cc];
__device__ bf16 g_wph_h[Ee*Cc], g_wph_l[Ee*Cc];
__device__ bf16 g_wg_h [Ee*Cc], g_wg_l [Ee*Cc];
__device__ bf16 g_wo_h [Cc*Ee], g_wo_l [Cc*Ee];
__device__ float g_scl[Cc], g_off[Cc];

// ------------------- helpers -------------------
__device__ __forceinline__ u32 s2u(const void* p){
    u32 a; asm("{ .reg .u64 t; cvta.to.shared.u64 t, %1; cvt.u32.u64 %0, t; }" : "=r"(a) : "l"(p)); return a;
}
__device__ __forceinline__ void cpa16(u32 dst, const void* src, int valid){
    int sz = valid ? 16 : 0;
    asm volatile("cp.async.cg.shared.global [%0], [%1], 16, %2;" :: "r"(dst), "l"(src), "r"(sz));
}
#define CP_COMMIT() asm volatile("cp.async.commit_group;" ::: "memory")
#define CP_WAIT1()  asm volatile("cp.async.wait_group 1;" ::: "memory")

__device__ __forceinline__ void ldm4(u32* r, u32 addr){
    asm volatile("ldmatrix.sync.aligned.m8n8.x4.shared.b16 {%0,%1,%2,%3}, [%4];"
        : "=r"(r[0]), "=r"(r[1]), "=r"(r[2]), "=r"(r[3]) : "r"(addr));
}
__device__ __forceinline__ void mma16816(float* c, const u32* a, const u32* b){
    asm volatile("mma.sync.aligned.m16n8k16.row.col.f32.bf16.bf16.f32 "
        "{%0,%1,%2,%3}, {%4,%5,%6,%7}, {%8,%9}, {%0,%1,%2,%3};"
        : "+f"(c[0]), "+f"(c[1]), "+f"(c[2]), "+f"(c[3])
        : "r"(a[0]), "r"(a[1]), "r"(a[2]), "r"(a[3]), "r"(b[0]), "r"(b[1]));
}

// smem geometry: dense 64B rows (128 rows x 32 bf16), granule-swizzled:
//   physical 16B-granule = logical ^ ((row>>1)&3)
// -> conflict-free ldmatrix phases, 16B-aligned cp.async, tile = 8KB
#define TILEB  (128*64)        // 8192 B per 128x32 bf16 tile
#define STAGEB (4*TILEB)       // Ah, Al, Bh, Bl = 32768 B
#define NSTG   3
#define SMEMD  (NSTG*STAGEB)   // 98304 B -> 2 CTAs / SM

// ------------------- generic bf16-split warp-MMA GEMM -------------------
// C[z][o][n] = sum_k A[z][o][k] * B[z][n][k]   (both K-major, hi/lo split, 3 mma passes)
// OUTM: 0 fp32 out, 1 split bf16 hi/lo out
// BIASM: 0 none, 1 per-row bias[o], 2 per-col bias[n]
// BNM: 1 = v*scl[o]+off[o]+resid[z][o][n]
template<int OUTM, int BIASM, int BNM>
__global__ void __launch_bounds__(256, 2)
mma_gemm(const bf16* __restrict__ Ah, const bf16* __restrict__ Al, long sAz, int Arows,
         const bf16* __restrict__ Bh, const bf16* __restrict__ Bl, long sBz, int Brows,
         int K,
         float* __restrict__ Cf, bf16* __restrict__ Ch, bf16* __restrict__ Cl,
         long sCz, int ldC, int Crows, int Ccols,
         const float* __restrict__ bias, const float* __restrict__ scl,
         const float* __restrict__ off, const float* __restrict__ resid, long sRz)
{
    extern __shared__ char sm[];
    const int t   = threadIdx.x;
    const int wid = t >> 5, lid = t & 31;
    const int o0  = blockIdx.y * 128, n0 = blockIdx.x * 128;
    const int z   = blockIdx.z;
    const int wm  = wid & 3, wn = wid >> 2;   // warp tile 32x64

    const bf16* Ahz = Ah + (long)z * sAz;
    const bf16* Alz = Al + (long)z * sAz;
    const bf16* Bhz = Bh + (long)z * sBz;
    const bf16* Blz = Bl + (long)z * sBz;

    const u32 smb = s2u(sm);

    // per-thread cp.async indexing: 512 16B-granules per 128x32 tile, 2 per thread
    const int id0 = t, id1 = t + 256;
    const int r0 = id0 >> 2, ch0 = id0 & 3;
    const int r1 = id1 >> 2, ch1 = id1 & 3;
    const int ar0 = o0 + r0, ar1 = o0 + r1;
    const int br0 = n0 + r0, br1 = n0 + r1;
    const int av0 = ar0 < Arows, av1 = ar1 < Arows;
    const int bv0 = br0 < Brows, bv1 = br1 < Brows;
    const long aoff0 = (long)(av0 ? ar0 : 0) * K + ch0 * 8;
    const long aoff1 = (long)(av1 ? ar1 : 0) * K + ch1 * 8;
    const long boff0 = (long)(bv0 ? br0 : 0) * K + ch0 * 8;
    const long boff1 = (long)(bv1 ? br1 : 0) * K + ch1 * 8;
    // swizzled smem destinations
    const u32 dst0 = (u32)(r0 * 64 + (ch0 ^ ((r0 >> 1) & 3)) * 16);
    const u32 dst1 = (u32)(r1 * 64 + (ch1 ^ ((r1 >> 1) & 3)) * 16);

    auto load_stage = [&](int st, int kb){
        u32 b = smb + st * STAGEB;
        long ko = (long)kb * 32;
        cpa16(b + dst0,             Ahz + aoff0 + ko, av0);
        cpa16(b + dst1,             Ahz + aoff1 + ko, av1);
        cpa16(b + TILEB   + dst0,   Alz + aoff0 + ko, av0);
        cpa16(b + TILEB   + dst1,   Alz + aoff1 + ko, av1);
        cpa16(b + 2*TILEB + dst0,   Bhz + boff0 + ko, bv0);
        cpa16(b + 2*TILEB + dst1,   Bhz + boff1 + ko, bv1);
        cpa16(b + 3*TILEB + dst0,   Blz + boff0 + ko, bv0);
        cpa16(b + 3*TILEB + dst1,   Blz + boff1 + ko, bv1);
        CP_COMMIT();
    };

    // ldmatrix lane geometry: row base + per-row swizzle key
    u32 arowb[2], aswz[2], browb[4], bswz[4];
#pragma unroll
    for (int i = 0; i < 2; i++){
        int r = wm*32 + i*16 + (lid & 15);
        arowb[i] = (u32)(r * 64);
        aswz[i]  = (u32)((r >> 1) & 3);
    }
    const u32 glA = (u32)(lid >> 4);        // logical granule 0/1 (ks adds 2)
#pragma unroll
    for (int j = 0; j < 4; j++){
        int r = wn*64 + j*16 + (lid & 7) + ((lid & 16) >> 1);
        browb[j] = (u32)(r * 64);
        bswz[j]  = (u32)((r >> 1) & 3);
    }
    const u32 glB = (u32)((lid >> 3) & 1);

    float acc[2][8][4];
#pragma unroll
    for (int i = 0; i < 2; i++)
#pragma unroll
        for (int j = 0; j < 8; j++)
#pragma unroll
            for (int k = 0; k < 4; k++) acc[i][j][k] = 0.f;

    const int nkb = K >> 5;
    // prologue: fill stages 0 and 1
    load_stage(0, 0);
    load_stage(1, 1);

    int cur = 0;    // stage holding kb
    int nxt = 2;    // stage to fill with kb+2
    for (int kb = 0; kb < nkb; kb++){
        CP_WAIT1();          // group kb landed (<=1 group in flight)
        __syncthreads();     // all warps done with stage `nxt` (= stage of kb-1)
        if (kb + 2 < nkb) load_stage(nxt, kb + 2);
        else              CP_COMMIT();   // empty group keeps wait_group 1 pacing

        const u32 base = smb + cur * STAGEB;
#pragma unroll
        for (int ks = 0; ks < 2; ks++){
            const u32 kg = (u32)(ks << 1);
            u32 ah[2][4], al[2][4], bh[4][4], bl[4][4];
#pragma unroll
            for (int i = 0; i < 2; i++){
                u32 ao = arowb[i] + (((glA | kg) ^ aswz[i]) << 4);
                ldm4(ah[i], base + ao);
                ldm4(al[i], base + TILEB + ao);
            }
#pragma unroll
            for (int j = 0; j < 4; j++){
                u32 bo = browb[j] + (((glB | kg) ^ bswz[j]) << 4);
                ldm4(bh[j], base + 2*TILEB + bo);
                ldm4(bl[j], base + 3*TILEB + bo);
            }
#pragma unroll
            for (int i = 0; i < 2; i++){
#pragma unroll
                for (int j8 = 0; j8 < 8; j8++){
                    const u32* bhp = &bh[j8 >> 1][(j8 & 1) * 2];
                    const u32* blp = &bl[j8 >> 1][(j8 & 1) * 2];
                    mma16816(acc[i][j8], ah[i], bhp);   // hi*hi
                    mma16816(acc[i][j8], ah[i], blp);   // hi*lo
                    mma16816(acc[i][j8], al[i], bhp);   // lo*hi
                }
            }
        }
        cur = (cur == NSTG - 1) ? 0 : cur + 1;
        nxt = (nxt == NSTG - 1) ? 0 : nxt + 1;
    }

    // ------------------- epilogue -------------------
    const int q = lid >> 2, tq = lid & 3;
    const int rbase = o0 + wm * 32;
    const int cbase = n0 + wn * 64;
#pragma unroll
    for (int i = 0; i < 2; i++){
#pragma unroll
        for (int half = 0; half < 2; half++){
            const int row = rbase + i * 16 + q + half * 8;
            if (row >= Crows) continue;
            float brow = 0.f, sc_r = 0.f, of_r = 0.f;
            if (BIASM == 1) brow = bias[row];
            if (BNM == 1){ sc_r = scl[row]; of_r = off[row]; }
            const float* rrow = (BNM == 1) ? (resid + (long)z * sRz + (long)row * ldC) : nullptr;
            float* cfrow = (OUTM == 0) ? (Cf + (long)z * sCz + (long)row * ldC) : nullptr;
            bf16* chrow  = (OUTM == 1) ? (Ch + (long)z * sCz + (long)row * ldC) : nullptr;
            bf16* clrow  = (OUTM == 1) ? (Cl + (long)z * sCz + (long)row * ldC) : nullptr;
#pragma unroll
            for (int j8 = 0; j8 < 8; j8++){
                const int col = cbase + j8 * 8 + tq * 2;
                if (col >= Ccols) continue;
                float v0 = acc[i][j8][half * 2 + 0];
                float v1 = acc[i][j8][half * 2 + 1];
                if (BIASM == 1){ v0 += brow; v1 += brow; }
                if (BIASM == 2){ v0 += bias[col]; v1 += bias[col + 1]; }
                if (BNM == 1){
                    v0 = v0 * sc_r + of_r + rrow[col];
                    v1 = v1 * sc_r + of_r + rrow[col + 1];
                }
                if (OUTM == 0){
                    *(float2*)(cfrow + col) = make_float2(v0, v1);
                } else {
                    bf16 h0 = __float2bfloat16(v0);
                    bf16 h1 = __float2bfloat16(v1);
                    bf16 l0 = __float2bfloat16(v0 - __bfloat162float(h0));
                    bf16 l1 = __float2bfloat16(v1 - __bfloat162float(h1));
                    u32 hp = ((u32)__bfloat16_as_ushort(h1) << 16) | __bfloat16_as_ushort(h0);
                    u32 lp = ((u32)__bfloat16_as_ushort(l1) << 16) | __bfloat16_as_ushort(l0);
                    *(u32*)(chrow + col) = hp;
                    *(u32*)(clrow + col) = lp;
                }
            }
        }
    }
}

// ------------------- conversion kernels -------------------
// split all 4 weight matrices in one launch (each Ee*Cc = Cc*Ee elements)
__global__ void wsplit4(const float* __restrict__ w0, const float* __restrict__ w1,
                        const float* __restrict__ w2, const float* __restrict__ w3,
                        bf16* __restrict__ h0, bf16* __restrict__ l0,
                        bf16* __restrict__ h1, bf16* __restrict__ l1,
                        bf16* __restrict__ h2, bf16* __restrict__ l2,
                        bf16* __restrict__ h3, bf16* __restrict__ l3){
    const long n = (long)Ee * Cc;
    long i = (long)blockIdx.x * blockDim.x + threadIdx.x;
    if (i >= n) return;
    const float* in; bf16 *hi, *lo;
    switch (blockIdx.y){
        case 0: in = w0; hi = h0; lo = l0; break;
        case 1: in = w1; hi = h1; lo = l1; break;
        case 2: in = w2; hi = h2; lo = l2; break;
        default:in = w3; hi = h3; lo = l3; break;
    }
    float v = in[i];
    bf16 h = __float2bfloat16(v);
    hi[i] = h;
    lo[i] = __float2bfloat16(v - __bfloat162float(h));
}

// x [B,C,N] -> xT hi/lo [B,N,C]
__global__ void xpose_split(const float* __restrict__ x,
                            bf16* __restrict__ oh, bf16* __restrict__ ol){
    __shared__ float tile[32][33];
    const int tx = threadIdx.x, ty = threadIdx.y;
    const int n0 = blockIdx.x * 32, c0 = blockIdx.y * 32, z = blockIdx.z;
    const float* xz = x + (long)z * Cc * NN;
#pragma unroll
    for (int j = 0; j < 4; j++){
        int c = c0 + ty + j * 8;
        tile[ty + j * 8][tx] = xz[(long)c * NN + n0 + tx];
    }
    __syncthreads();
    bf16* ohz = oh + (long)z * NN * Cc;
    bf16* olz = ol + (long)z * NN * Cc;
#pragma unroll
    for (int j = 0; j < 4; j++){
        int n = n0 + ty + j * 8;
        float v = tile[tx][ty + j * 8];
        bf16 h = __float2bfloat16(v);
        long idx = (long)n * Cc + c0 + tx;
        ohz[idx] = h;
        olz[idx] = __float2bfloat16(v - __bfloat162float(h));
    }
}

// maxpool (1,2,2) + transpose + split: x [B,C,T,28,28] -> xsubT hi/lo [B,M,C]
__global__ void pool_xpose_split(const float* __restrict__ x,
                                 bf16* __restrict__ oh, bf16* __restrict__ ol){
    __shared__ float tile[32][33];
    const int tx = threadIdx.x, ty = threadIdx.y;
    const int m0 = blockIdx.x * 32, c0 = blockIdx.y * 32, z = blockIdx.z;
    const int m = m0 + tx;
    const int t_ = m / 196, r = m % 196, h2 = r / 14, w2 = r % 14;
#pragma unroll
    for (int j = 0; j < 4; j++){
        int c = c0 + ty + j * 8;
        const float* p = x + ((((long)z * Cc + c) * Tt + t_) * 28 + h2 * 2) * 28 + w2 * 2;
        float v = fmaxf(fmaxf(p[0], p[1]), fmaxf(p[28], p[29]));
        tile[ty + j * 8][tx] = v;
    }
    __syncthreads();
    bf16* ohz = oh + (long)z * MM * Cc;
    bf16* olz = ol + (long)z * MM * Cc;
#pragma unroll
    for (int j = 0; j < 4; j++){
        int mw = m0 + ty + j * 8;
        float v = tile[tx][ty + j * 8];
        bf16 h = __float2bfloat16(v);
        long idx = (long)mw * Cc + c0 + tx;
        ohz[idx] = h;
        olz[idx] = __float2bfloat16(v - __bfloat162float(h));
    }
}

// row softmax over 1568 keys -> split bf16 P
__global__ void softmax_split(const float* __restrict__ S,
                              bf16* __restrict__ ph, bf16* __restrict__ pl){
    const long row = blockIdx.x;
    const float* p = S + row * MM;
    const int t = threadIdx.x;
    float v[7];
    float lm = -3.4e38f;
#pragma unroll
    for (int it = 0; it < 7; it++){
        int idx = t + it * 256;
        v[it] = (idx < MM) ? p[idx] : -3.4e38f;
        lm = fmaxf(lm, v[it]);
    }
    __shared__ float red[256];
    red[t] = lm; __syncthreads();
    for (int s = 128; s > 0; s >>= 1){ if (t < s) red[t] = fmaxf(red[t], red[t + s]); __syncthreads(); }
    float m = red[0];
    __syncthreads();
    float ls = 0.f;
#pragma unroll
    for (int it = 0; it < 7; it++){
        int idx = t + it * 256;
        if (idx < MM){ float e = __expf(v[it] - m); v[it] = e; ls += e; }
    }
    red[t] = ls; __syncthreads();
    for (int s = 128; s > 0; s >>= 1){ if (t < s) red[t] += red[t + s]; __syncthreads(); }
    float inv = 1.f / red[0];
    bf16* phr = ph + row * MM;
    bf16* plr = pl + row * MM;
#pragma unroll
    for (int it = 0; it < 7; it++){
        int idx = t + it * 256;
        if (idx < MM){
            float val = v[it] * inv;
            bf16 h = __float2bfloat16(val);
            phr[idx] = h;
            plr[idx] = __float2bfloat16(val - __bfloat162float(h));
        }
    }
}

__global__ void affine_kernel(const float* __restrict__ bo, const float* __restrict__ gm,
                              const float* __restrict__ bt, const float* __restrict__ mn,
                              const float* __restrict__ vr,
                              float* __restrict__ scl, float* __restrict__ off){
    int c = blockIdx.x * blockDim.x + threadIdx.x;
    if (c < Cc){
        float s = gm[c] * rsqrtf(vr[c] + EPSV);
        scl[c] = s;
        off[c] = (bo[c] - mn[c]) * s + bt[c];
    }
}

// ------------------- launch -------------------
extern "C" void kernel_launch(void* const* d_in, const int* in_sizes, int n_in,
                              void* d_out, int out_size){
    const float* x       = (const float*)d_in[0];
    const float* w_theta = (const float*)d_in[1];
    const float* b_theta = (const float*)d_in[2];
    const float* w_phi   = (const float*)d_in[3];
    const float* b_phi   = (const float*)d_in[4];
    const float* w_g     = (const float*)d_in[5];
    const float* b_g     = (const float*)d_in[6];
    const float* w_out   = (const float*)d_in[7];
    const float* b_out   = (const float*)d_in[8];
    const float* bn_gm   = (const float*)d_in[9];
    const float* bn_bt   = (const float*)d_in[10];
    const float* bn_mn   = (const float*)d_in[11];
    const float* bn_vr   = (const float*)d_in[12];
    float* out = (float*)d_out;

    bf16 *xT_h, *xT_l, *xsT_h, *xsT_l, *th_h, *th_l, *ph_h, *ph_l;
    bf16 *gg_h, *gg_l, *p_h, *p_l, *y_h, *y_l;
    bf16 *wth_h, *wth_l, *wph_h, *wph_l, *wg_h, *wg_l, *wo_h, *wo_l;
    float *sc, *scl, *off;
    cudaGetSymbolAddress((void**)&xT_h, g_xT_h);  cudaGetSymbolAddress((void**)&xT_l, g_xT_l);
    cudaGetSymbolAddress((void**)&xsT_h, g_xsT_h);cudaGetSymbolAddress((void**)&xsT_l, g_xsT_l);
    cudaGetSymbolAddress((void**)&th_h, g_th_h);  cudaGetSymbolAddress((void**)&th_l, g_th_l);
    cudaGetSymbolAddress((void**)&ph_h, g_ph_h);  cudaGetSymbolAddress((void**)&ph_l, g_ph_l);
    cudaGetSymbolAddress((void**)&gg_h, g_g_h);   cudaGetSymbolAddress((void**)&gg_l, g_g_l);
    cudaGetSymbolAddress((void**)&sc, g_sc);
    cudaGetSymbolAddress((void**)&p_h, g_p_h);    cudaGetSymbolAddress((void**)&p_l, g_p_l);
    cudaGetSymbolAddress((void**)&y_h, g_y_h);    cudaGetSymbolAddress((void**)&y_l, g_y_l);
    cudaGetSymbolAddress((void**)&wth_h, g_wth_h);cudaGetSymbolAddress((void**)&wth_l, g_wth_l);
    cudaGetSymbolAddress((void**)&wph_h, g_wph_h);cudaGetSymbolAddress((void**)&wph_l, g_wph_l);
    cudaGetSymbolAddress((void**)&wg_h, g_wg_h);  cudaGetSymbolAddress((void**)&wg_l, g_wg_l);
    cudaGetSymbolAddress((void**)&wo_h, g_wo_h);  cudaGetSymbolAddress((void**)&wo_l, g_wo_l);
    cudaGetSymbolAddress((void**)&scl, g_scl);    cudaGetSymbolAddress((void**)&off, g_off);

    cudaFuncSetAttribute(mma_gemm<1,2,0>, cudaFuncAttributeMaxDynamicSharedMemorySize, SMEMD);
    cudaFuncSetAttribute(mma_gemm<1,1,0>, cudaFuncAttributeMaxDynamicSharedMemorySize, SMEMD);
    cudaFuncSetAttribute(mma_gemm<0,0,0>, cudaFuncAttributeMaxDynamicSharedMemorySize, SMEMD);
    cudaFuncSetAttribute(mma_gemm<1,0,0>, cudaFuncAttributeMaxDynamicSharedMemorySize, SMEMD);
    cudaFuncSetAttribute(mma_gemm<0,0,1>, cudaFuncAttributeMaxDynamicSharedMemorySize, SMEMD);

    // launch 0
    affine_kernel<<<(Cc + 255) / 256, 256>>>(b_out, bn_gm, bn_bt, bn_mn, bn_vr, scl, off);

    // launch 1: all 4 weight splits
    wsplit4<<<dim3((Ee * Cc + 255) / 256, 4), 256>>>(
        w_theta, w_phi, w_g, w_out,
        wth_h, wth_l, wph_h, wph_l, wg_h, wg_l, wo_h, wo_l);

    // launch 2
    xpose_split<<<dim3(NN / 32, Cc / 32, Bb), dim3(32, 8)>>>(x, xT_h, xT_l);

    // launch 3 (ncu capture lands here): thetaT[n,e] = sum_c xT[n,c] w_theta[e,c] + b_theta[e]
    mma_gemm<1,2,0><<<dim3(Ee / 128, NN / 128, Bb), 256, SMEMD>>>(
        xT_h, xT_l, (long)NN * Cc, NN,
        wth_h, wth_l, 0L, Ee, Cc,
        nullptr, th_h, th_l, (long)NN * Ee, Ee, NN, Ee,
        b_theta, nullptr, nullptr, nullptr, 0L);

    // launch 4
    pool_xpose_split<<<dim3(MM / 32, Cc / 32, Bb), dim3(32, 8)>>>(x, xsT_h, xsT_l);

    // launch 5: phiT[m,e] = sum_c xsT[m,c] w_phi[e,c] + b_phi[e]
    mma_gemm<1,2,0><<<dim3(Ee / 128, (MM + 127) / 128, Bb), 256, SMEMD>>>(
        xsT_h, xsT_l, (long)MM * Cc, MM,
        wph_h, wph_l, 0L, Ee, Cc,
        nullptr, ph_h, ph_l, (long)MM * Ee, Ee, MM, Ee,
        b_phi, nullptr, nullptr, nullptr, 0L);

    // launch 6: g[e,m] = sum_c w_g[e,c] xsT[m,c] + b_g[e]
    mma_gemm<1,1,0><<<dim3((MM + 127) / 128, Ee / 128, Bb), 256, SMEMD>>>(
        wg_h, wg_l, 0L, Ee,
        xsT_h, xsT_l, (long)MM * Cc, MM, Cc,
        nullptr, gg_h, gg_l, (long)Ee * MM, MM, Ee, MM,
        b_g, nullptr, nullptr, nullptr, 0L);

    // launch 7: scores[n,m] = sum_e thetaT[n,e] phiT[m,e]
    mma_gemm<0,0,0><<<dim3((MM + 127) / 128, NN / 128, Bb), 256, SMEMD>>>(
        th_h, th_l, (long)NN * Ee, NN,
        ph_h, ph_l, (long)MM * Ee, MM, Ee,
        sc, nullptr, nullptr, (long)NN * MM, MM, NN, MM,
        nullptr, nullptr, nullptr, nullptr, 0L);

    // launch 8
    softmax_split<<<Bb * NN, 256>>>(sc, p_h, p_l);

    // launch 9: yT[n,e] = sum_m P[n,m] g[e,m]
    mma_gemm<1,0,0><<<dim3(Ee / 128, NN / 128, Bb), 256, SMEMD>>>(
        p_h, p_l, (long)NN * MM, NN,
        gg_h, gg_l, (long)Ee * MM, Ee, MM,
        nullptr, y_h, y_l, (long)NN * Ee, Ee, NN, Ee,
        nullptr, nullptr, nullptr, nullptr, 0L);

    // launch 10: out[c,n] = BN(sum_e w_out[c,e] yT[n,e]) + x[c,n]
    mma_gemm<0,0,1><<<dim3(NN / 128, Cc / 128, Bb), 256, SMEMD>>>(
        wo_h, wo_l, 0L, Cc,
        y_h, y_l, (long)NN * Ee, NN, Ee,
        out, nullptr, nullptr, (long)Cc * NN, NN, Cc, NN,
        nullptr, scl, off, x, (long)Cc * NN);
}

// round 15
// speedup vs baseline: 2.2758x; 1.0837x over previous
#include <cuda_runtime.h>
#include <cuda_bf16.h>
#include <cuda_fp16.h>
#include <cstdint>

#define Bb 8
#define Cc 1024
#define Tt 8
#define Ee 512
#define NN 6272
#define MM 1568
#define EPSV 1e-5f

typedef unsigned int u32;
typedef unsigned long long u64;
typedef __nv_bfloat16 bf16;

// ------------------- device scratch -------------------
__device__ bf16 g_xT_h[(long)Bb*NN*Cc], g_xT_l[(long)Bb*NN*Cc];     // x^T [B,N,C]
__device__ bf16 g_xsT_h[(long)Bb*MM*Cc], g_xsT_l[(long)Bb*MM*Cc];   // xsub^T [B,M,C]
__device__ bf16 g_th_h[(long)Bb*NN*Ee], g_th_l[(long)Bb*NN*Ee];     // theta^T [B,N,E]
__device__ bf16 g_ph_h[(long)Bb*MM*Ee], g_ph_l[(long)Bb*MM*Ee];     // phi^T [B,M,E]
__device__ bf16 g_g_h[(long)Bb*Ee*MM], g_g_l[(long)Bb*Ee*MM];       // g [B,E,M] (fp16 bits)
__device__ float g_sc[(long)Bb*NN*MM];                              // scores [B,N,M]
__device__ bf16 g_p_h[(long)Bb*NN*MM];                              // P [B,N,M] fp16 bits
__device__ bf16 g_y_h[(long)Bb*NN*Ee], g_y_l[(long)Bb*NN*Ee];       // y^T [B,N,E]
__device__ bf16 g_wth_h[Ee*Cc], g_wth_l[Ee*Cc];
__device__ bf16 g_wph_h[Ee*Cc], g_wph_l[Ee*Cc];
__device__ bf16 g_wg_h [Ee*Cc], g_wg_l [Ee*Cc];
__device__ bf16 g_wo_h [Cc*Ee], g_wo_l [Cc*Ee];
__device__ float g_scl[Cc], g_off[Cc];

// ------------------- helpers -------------------
__device__ __forceinline__ u32 s2u(const void* p){
    u32 a; asm("{ .reg .u64 t; cvta.to.shared.u64 t, %1; cvt.u32.u64 %0, t; }" : "=r"(a) : "l"(p)); return a;
}
__device__ __forceinline__ void cpa16(u32 dst, const void* src, int valid){
    int sz = valid ? 16 : 0;
    asm volatile("cp.async.cg.shared.global [%0], [%1], 16, %2;" :: "r"(dst), "l"(src), "r"(sz));
}
#define CP_COMMIT() asm volatile("cp.async.commit_group;" ::: "memory")
#define CP_WAIT1()  asm volatile("cp.async.wait_group 1;" ::: "memory")

__device__ __forceinline__ void ldm4(u32* r, u32 addr){
    asm volatile("ldmatrix.sync.aligned.m8n8.x4.shared.b16 {%0,%1,%2,%3}, [%4];"
        : "=r"(r[0]), "=r"(r[1]), "=r"(r[2]), "=r"(r[3]) : "r"(addr));
}
template<int PREC>
__device__ __forceinline__ void mmaT(float* c, const u32* a, const u32* b){
    if (PREC == 0){
        asm volatile("mma.sync.aligned.m16n8k16.row.col.f32.bf16.bf16.f32 "
            "{%0,%1,%2,%3}, {%4,%5,%6,%7}, {%8,%9}, {%0,%1,%2,%3};"
            : "+f"(c[0]), "+f"(c[1]), "+f"(c[2]), "+f"(c[3])
            : "r"(a[0]), "r"(a[1]), "r"(a[2]), "r"(a[3]), "r"(b[0]), "r"(b[1]));
    } else {
        asm volatile("mma.sync.aligned.m16n8k16.row.col.f32.f16.f16.f32 "
            "{%0,%1,%2,%3}, {%4,%5,%6,%7}, {%8,%9}, {%0,%1,%2,%3};"
            : "+f"(c[0]), "+f"(c[1]), "+f"(c[2]), "+f"(c[3])
            : "r"(a[0]), "r"(a[1]), "r"(a[2]), "r"(a[3]), "r"(b[0]), "r"(b[1]));
    }
}

// smem geometry: dense 64B rows (128 rows x 32 halfword), granule-swizzled:
//   physical 16B-granule = logical ^ ((row>>1)&3)
#define TILEB  (128*64)        // 8192 B per 128x32 tile
#define NSTG   3
#define SMEMD0 (NSTG*4*TILEB)  // bf16 3-pass: Ah,Al,Bh,Bl = 98304 B
#define SMEMD1 (NSTG*3*TILEB)  // fp16 2-pass: A,Bh,Bl     = 73728 B

// ------------------- generic split warp-MMA GEMM -------------------
// C[z][o][n] = sum_k A[z][o][k] * B[z][n][k]   (both K-major)
// PREC 0: bf16 hi/lo both operands, 3 passes. PREC 1: A single fp16, B fp16 hi/lo, 2 passes.
// OUTM: 0 fp32 out, 1 bf16 hi/lo out, 2 fp16 hi/lo out
// BIASM: 0 none, 1 per-row bias[o], 2 per-col bias[n]
// BNM: 1 = v*scl[o]+off[o]+resid[z][o][n]
template<int OUTM, int BIASM, int BNM, int PREC>
__global__ void __launch_bounds__(256, 2)
mma_gemm(const bf16* __restrict__ Ah, const bf16* __restrict__ Al, long sAz, int Arows,
         const bf16* __restrict__ Bh, const bf16* __restrict__ Bl, long sBz, int Brows,
         int K,
         float* __restrict__ Cf, bf16* __restrict__ Ch, bf16* __restrict__ Cl,
         long sCz, int ldC, int Crows, int Ccols,
         const float* __restrict__ bias, const float* __restrict__ scl,
         const float* __restrict__ off, const float* __restrict__ resid, long sRz)
{
    extern __shared__ char sm[];
    constexpr int NT = (PREC == 0) ? 4 : 3;        // tiles per stage
    constexpr int STAGEB = NT * TILEB;
    const int t   = threadIdx.x;
    const int wid = t >> 5, lid = t & 31;
    const int o0  = blockIdx.y * 128, n0 = blockIdx.x * 128;
    const int z   = blockIdx.z;
    const int wm  = wid & 3, wn = wid >> 2;   // warp tile 32x64

    const bf16* Ahz = Ah + (long)z * sAz;
    const bf16* Alz = Al + (long)z * sAz;
    const bf16* Bhz = Bh + (long)z * sBz;
    const bf16* Blz = Bl + (long)z * sBz;

    const u32 smb = s2u(sm);

    // per-thread cp.async indexing: 512 16B-granules per 128x32 tile, 2 per thread
    const int id0 = t, id1 = t + 256;
    const int r0 = id0 >> 2, ch0 = id0 & 3;
    const int r1 = id1 >> 2, ch1 = id1 & 3;
    const int ar0 = o0 + r0, ar1 = o0 + r1;
    const int br0 = n0 + r0, br1 = n0 + r1;
    const int av0 = ar0 < Arows, av1 = ar1 < Arows;
    const int bv0 = br0 < Brows, bv1 = br1 < Brows;
    const long aoff0 = (long)(av0 ? ar0 : 0) * K + ch0 * 8;
    const long aoff1 = (long)(av1 ? ar1 : 0) * K + ch1 * 8;
    const long boff0 = (long)(bv0 ? br0 : 0) * K + ch0 * 8;
    const long boff1 = (long)(bv1 ? br1 : 0) * K + ch1 * 8;
    // swizzled smem destinations
    const u32 dst0 = (u32)(r0 * 64 + (ch0 ^ ((r0 >> 1) & 3)) * 16);
    const u32 dst1 = (u32)(r1 * 64 + (ch1 ^ ((r1 >> 1) & 3)) * 16);

    auto load_stage = [&](int st, int kb){
        u32 b = smb + st * STAGEB;
        long ko = (long)kb * 32;
        if (PREC == 0){
            cpa16(b + dst0,             Ahz + aoff0 + ko, av0);
            cpa16(b + dst1,             Ahz + aoff1 + ko, av1);
            cpa16(b + TILEB   + dst0,   Alz + aoff0 + ko, av0);
            cpa16(b + TILEB   + dst1,   Alz + aoff1 + ko, av1);
            cpa16(b + 2*TILEB + dst0,   Bhz + boff0 + ko, bv0);
            cpa16(b + 2*TILEB + dst1,   Bhz + boff1 + ko, bv1);
            cpa16(b + 3*TILEB + dst0,   Blz + boff0 + ko, bv0);
            cpa16(b + 3*TILEB + dst1,   Blz + boff1 + ko, bv1);
        } else {
            cpa16(b + dst0,             Ahz + aoff0 + ko, av0);
            cpa16(b + dst1,             Ahz + aoff1 + ko, av1);
            cpa16(b + TILEB   + dst0,   Bhz + boff0 + ko, bv0);
            cpa16(b + TILEB   + dst1,   Bhz + boff1 + ko, bv1);
            cpa16(b + 2*TILEB + dst0,   Blz + boff0 + ko, bv0);
            cpa16(b + 2*TILEB + dst1,   Blz + boff1 + ko, bv1);
        }
        CP_COMMIT();
    };

    // ldmatrix lane geometry: row base + per-row swizzle key
    u32 arowb[2], aswz[2], browb[4], bswz[4];
#pragma unroll
    for (int i = 0; i < 2; i++){
        int r = wm*32 + i*16 + (lid & 15);
        arowb[i] = (u32)(r * 64);
        aswz[i]  = (u32)((r >> 1) & 3);
    }
    const u32 glA = (u32)(lid >> 4);        // logical granule 0/1 (ks adds 2)
#pragma unroll
    for (int j = 0; j < 4; j++){
        int r = wn*64 + j*16 + (lid & 7) + ((lid & 16) >> 1);
        browb[j] = (u32)(r * 64);
        bswz[j]  = (u32)((r >> 1) & 3);
    }
    const u32 glB = (u32)((lid >> 3) & 1);

    float acc[2][8][4];
#pragma unroll
    for (int i = 0; i < 2; i++)
#pragma unroll
        for (int j = 0; j < 8; j++)
#pragma unroll
            for (int k = 0; k < 4; k++) acc[i][j][k] = 0.f;

    const int nkb = K >> 5;
    // prologue: fill stages 0 and 1
    load_stage(0, 0);
    load_stage(1, 1);

    int cur = 0;    // stage holding kb
    int nxt = 2;    // stage to fill with kb+2
    for (int kb = 0; kb < nkb; kb++){
        CP_WAIT1();          // own group kb landed (1 group may remain in flight)
        __syncthreads();     // ALL threads passed their wait -> group kb globally visible;
                             // also: everyone done reading stage `nxt` (= stage of kb-1)
        if (kb + 2 < nkb) load_stage(nxt, kb + 2);
        else              CP_COMMIT();   // empty group keeps wait_group pacing

        const u32 base = smb + cur * STAGEB;
#pragma unroll
        for (int ks = 0; ks < 2; ks++){
            const u32 kg = (u32)(ks << 1);
            if (PREC == 0){
                u32 ah[2][4], al[2][4], bh[4][4], bl[4][4];
#pragma unroll
                for (int i = 0; i < 2; i++){
                    u32 ao = arowb[i] + (((glA | kg) ^ aswz[i]) << 4);
                    ldm4(ah[i], base + ao);
                    ldm4(al[i], base + TILEB + ao);
                }
#pragma unroll
                for (int j = 0; j < 4; j++){
                    u32 bo = browb[j] + (((glB | kg) ^ bswz[j]) << 4);
                    ldm4(bh[j], base + 2*TILEB + bo);
                    ldm4(bl[j], base + 3*TILEB + bo);
                }
#pragma unroll
                for (int i = 0; i < 2; i++){
#pragma unroll
                    for (int j8 = 0; j8 < 8; j8++){
                        const u32* bhp = &bh[j8 >> 1][(j8 & 1) * 2];
                        const u32* blp = &bl[j8 >> 1][(j8 & 1) * 2];
                        mmaT<0>(acc[i][j8], ah[i], bhp);   // hi*hi
                        mmaT<0>(acc[i][j8], ah[i], blp);   // hi*lo
                        mmaT<0>(acc[i][j8], al[i], bhp);   // lo*hi
                    }
                }
            } else {
                u32 a[2][4], bh[4][4], bl[4][4];
#pragma unroll
                for (int i = 0; i < 2; i++){
                    u32 ao = arowb[i] + (((glA | kg) ^ aswz[i]) << 4);
                    ldm4(a[i], base + ao);
                }
#pragma unroll
                for (int j = 0; j < 4; j++){
                    u32 bo = browb[j] + (((glB | kg) ^ bswz[j]) << 4);
                    ldm4(bh[j], base + TILEB + bo);
                    ldm4(bl[j], base + 2*TILEB + bo);
                }
#pragma unroll
                for (int i = 0; i < 2; i++){
#pragma unroll
                    for (int j8 = 0; j8 < 8; j8++){
                        const u32* bhp = &bh[j8 >> 1][(j8 & 1) * 2];
                        const u32* blp = &bl[j8 >> 1][(j8 & 1) * 2];
                        mmaT<1>(acc[i][j8], a[i], bhp);    // P*gh
                        mmaT<1>(acc[i][j8], a[i], blp);    // P*gl
                    }
                }
            }
        }
        cur = (cur == NSTG - 1) ? 0 : cur + 1;
        nxt = (nxt == NSTG - 1) ? 0 : nxt + 1;
    }

    // ------------------- epilogue -------------------
    const int q = lid >> 2, tq = lid & 3;
    const int rbase = o0 + wm * 32;
    const int cbase = n0 + wn * 64;
#pragma unroll
    for (int i = 0; i < 2; i++){
#pragma unroll
        for (int half = 0; half < 2; half++){
            const int row = rbase + i * 16 + q + half * 8;
            if (row >= Crows) continue;
            float brow = 0.f, sc_r = 0.f, of_r = 0.f;
            if (BIASM == 1) brow = bias[row];
            if (BNM == 1){ sc_r = scl[row]; of_r = off[row]; }
            const float* rrow = (BNM == 1) ? (resid + (long)z * sRz + (long)row * ldC) : nullptr;
            float* cfrow = (OUTM == 0) ? (Cf + (long)z * sCz + (long)row * ldC) : nullptr;
            bf16* chrow  = (OUTM != 0) ? (Ch + (long)z * sCz + (long)row * ldC) : nullptr;
            bf16* clrow  = (OUTM != 0) ? (Cl + (long)z * sCz + (long)row * ldC) : nullptr;
#pragma unroll
            for (int j8 = 0; j8 < 8; j8++){
                const int col = cbase + j8 * 8 + tq * 2;
                if (col >= Ccols) continue;
                float v0 = acc[i][j8][half * 2 + 0];
                float v1 = acc[i][j8][half * 2 + 1];
                if (BIASM == 1){ v0 += brow; v1 += brow; }
                if (BIASM == 2){ v0 += bias[col]; v1 += bias[col + 1]; }
                if (BNM == 1){
                    v0 = v0 * sc_r + of_r + rrow[col];
                    v1 = v1 * sc_r + of_r + rrow[col + 1];
                }
                if (OUTM == 0){
                    *(float2*)(cfrow + col) = make_float2(v0, v1);
                } else if (OUTM == 1){
                    bf16 h0 = __float2bfloat16(v0);
                    bf16 h1 = __float2bfloat16(v1);
                    bf16 l0 = __float2bfloat16(v0 - __bfloat162float(h0));
                    bf16 l1 = __float2bfloat16(v1 - __bfloat162float(h1));
                    u32 hp = ((u32)__bfloat16_as_ushort(h1) << 16) | __bfloat16_as_ushort(h0);
                    u32 lp = ((u32)__bfloat16_as_ushort(l1) << 16) | __bfloat16_as_ushort(l0);
                    *(u32*)(chrow + col) = hp;
                    *(u32*)(clrow + col) = lp;
                } else {
                    __half h0 = __float2half_rn(v0);
                    __half h1 = __float2half_rn(v1);
                    __half l0 = __float2half_rn(v0 - __half2float(h0));
                    __half l1 = __float2half_rn(v1 - __half2float(h1));
                    u32 hp = ((u32)__half_as_ushort(h1) << 16) | __half_as_ushort(h0);
                    u32 lp = ((u32)__half_as_ushort(l1) << 16) | __half_as_ushort(l0);
                    *(u32*)(chrow + col) = hp;
                    *(u32*)(clrow + col) = lp;
                }
            }
        }
    }
}

// ------------------- conversion kernels -------------------
__global__ void wsplit4(const float* __restrict__ w0, const float* __restrict__ w1,
                        const float* __restrict__ w2, const float* __restrict__ w3,
                        bf16* __restrict__ h0, bf16* __restrict__ l0,
                        bf16* __restrict__ h1, bf16* __restrict__ l1,
                        bf16* __restrict__ h2, bf16* __restrict__ l2,
                        bf16* __restrict__ h3, bf16* __restrict__ l3){
    const long n = (long)Ee * Cc;
    long i = (long)blockIdx.x * blockDim.x + threadIdx.x;
    if (i >= n) return;
    const float* in; bf16 *hi, *lo;
    switch (blockIdx.y){
        case 0: in = w0; hi = h0; lo = l0; break;
        case 1: in = w1; hi = h1; lo = l1; break;
        case 2: in = w2; hi = h2; lo = l2; break;
        default:in = w3; hi = h3; lo = l3; break;
    }
    float v = in[i];
    bf16 h = __float2bfloat16(v);
    hi[i] = h;
    lo[i] = __float2bfloat16(v - __bfloat162float(h));
}

// x [B,C,N] -> xT hi/lo [B,N,C]
__global__ void xpose_split(const float* __restrict__ x,
                            bf16* __restrict__ oh, bf16* __restrict__ ol){
    __shared__ float tile[32][33];
    const int tx = threadIdx.x, ty = threadIdx.y;
    const int n0 = blockIdx.x * 32, c0 = blockIdx.y * 32, z = blockIdx.z;
    const float* xz = x + (long)z * Cc * NN;
#pragma unroll
    for (int j = 0; j < 4; j++){
        int c = c0 + ty + j * 8;
        tile[ty + j * 8][tx] = xz[(long)c * NN + n0 + tx];
    }
    __syncthreads();
    bf16* ohz = oh + (long)z * NN * Cc;
    bf16* olz = ol + (long)z * NN * Cc;
#pragma unroll
    for (int j = 0; j < 4; j++){
        int n = n0 + ty + j * 8;
        float v = tile[tx][ty + j * 8];
        bf16 h = __float2bfloat16(v);
        long idx = (long)n * Cc + c0 + tx;
        ohz[idx] = h;
        olz[idx] = __float2bfloat16(v - __bfloat162float(h));
    }
}

// maxpool (1,2,2) + transpose + split: x [B,C,T,28,28] -> xsubT hi/lo [B,M,C]
__global__ void pool_xpose_split(const float* __restrict__ x,
                                 bf16* __restrict__ oh, bf16* __restrict__ ol){
    __shared__ float tile[32][33];
    const int tx = threadIdx.x, ty = threadIdx.y;
    const int m0 = blockIdx.x * 32, c0 = blockIdx.y * 32, z = blockIdx.z;
    const int m = m0 + tx;
    const int t_ = m / 196, r = m % 196, h2 = r / 14, w2 = r % 14;
#pragma unroll
    for (int j = 0; j < 4; j++){
        int c = c0 + ty + j * 8;
        const float* p = x + ((((long)z * Cc + c) * Tt + t_) * 28 + h2 * 2) * 28 + w2 * 2;
        float v = fmaxf(fmaxf(p[0], p[1]), fmaxf(p[28], p[29]));
        tile[ty + j * 8][tx] = v;
    }
    __syncthreads();
    bf16* ohz = oh + (long)z * MM * Cc;
    bf16* olz = ol + (long)z * MM * Cc;
#pragma unroll
    for (int j = 0; j < 4; j++){
        int mw = m0 + ty + j * 8;
        float v = tile[tx][ty + j * 8];
        bf16 h = __float2bfloat16(v);
        long idx = (long)mw * Cc + c0 + tx;
        ohz[idx] = h;
        olz[idx] = __float2bfloat16(v - __bfloat162float(h));
    }
}

// row softmax over 1568 keys -> single fp16 P
__global__ void softmax_fp16(const float* __restrict__ S, __half* __restrict__ ph){
    const long row = blockIdx.x;
    const float* p = S + row * MM;
    const int t = threadIdx.x;
    float v[7];
    float lm = -3.4e38f;
#pragma unroll
    for (int it = 0; it < 7; it++){
        int idx = t + it * 256;
        v[it] = (idx < MM) ? p[idx] : -3.4e38f;
        lm = fmaxf(lm, v[it]);
    }
    __shared__ float red[256];
    red[t] = lm; __syncthreads();
    for (int s = 128; s > 0; s >>= 1){ if (t < s) red[t] = fmaxf(red[t], red[t + s]); __syncthreads(); }
    float m = red[0];
    __syncthreads();
    float ls = 0.f;
#pragma unroll
    for (int it = 0; it < 7; it++){
        int idx = t + it * 256;
        if (idx < MM){ float e = __expf(v[it] - m); v[it] = e; ls += e; }
    }
    red[t] = ls; __syncthreads();
    for (int s = 128; s > 0; s >>= 1){ if (t < s) red[t] += red[t + s]; __syncthreads(); }
    float inv = 1.f / red[0];
    __half* phr = ph + row * MM;
#pragma unroll
    for (int it = 0; it < 7; it++){
        int idx = t + it * 256;
        if (idx < MM) phr[idx] = __float2half_rn(v[it] * inv);
    }
}

__global__ void affine_kernel(const float* __restrict__ bo, const float* __restrict__ gm,
                              const float* __restrict__ bt, const float* __restrict__ mn,
                              const float* __restrict__ vr,
                              float* __restrict__ scl, float* __restrict__ off){
    int c = blockIdx.x * blockDim.x + threadIdx.x;
    if (c < Cc){
        float s = gm[c] * rsqrtf(vr[c] + EPSV);
        scl[c] = s;
        off[c] = (bo[c] - mn[c]) * s + bt[c];
    }
}

// ------------------- launch -------------------
extern "C" void kernel_launch(void* const* d_in, const int* in_sizes, int n_in,
                              void* d_out, int out_size){
    const float* x       = (const float*)d_in[0];
    const float* w_theta = (const float*)d_in[1];
    const float* b_theta = (const float*)d_in[2];
    const float* w_phi   = (const float*)d_in[3];
    const float* b_phi   = (const float*)d_in[4];
    const float* w_g     = (const float*)d_in[5];
    const float* b_g     = (const float*)d_in[6];
    const float* w_out   = (const float*)d_in[7];
    const float* b_out   = (const float*)d_in[8];
    const float* bn_gm   = (const float*)d_in[9];
    const float* bn_bt   = (const float*)d_in[10];
    const float* bn_mn   = (const float*)d_in[11];
    const float* bn_vr   = (const float*)d_in[12];
    float* out = (float*)d_out;

    bf16 *xT_h, *xT_l, *xsT_h, *xsT_l, *th_h, *th_l, *ph_h, *ph_l;
    bf16 *gg_h, *gg_l, *p_h, *y_h, *y_l;
    bf16 *wth_h, *wth_l, *wph_h, *wph_l, *wg_h, *wg_l, *wo_h, *wo_l;
    float *sc, *scl, *off;
    cudaGetSymbolAddress((void**)&xT_h, g_xT_h);  cudaGetSymbolAddress((void**)&xT_l, g_xT_l);
    cudaGetSymbolAddress((void**)&xsT_h, g_xsT_h);cudaGetSymbolAddress((void**)&xsT_l, g_xsT_l);
    cudaGetSymbolAddress((void**)&th_h, g_th_h);  cudaGetSymbolAddress((void**)&th_l, g_th_l);
    cudaGetSymbolAddress((void**)&ph_h, g_ph_h);  cudaGetSymbolAddress((void**)&ph_l, g_ph_l);
    cudaGetSymbolAddress((void**)&gg_h, g_g_h);   cudaGetSymbolAddress((void**)&gg_l, g_g_l);
    cudaGetSymbolAddress((void**)&sc, g_sc);
    cudaGetSymbolAddress((void**)&p_h, g_p_h);
    cudaGetSymbolAddress((void**)&y_h, g_y_h);    cudaGetSymbolAddress((void**)&y_l, g_y_l);
    cudaGetSymbolAddress((void**)&wth_h, g_wth_h);cudaGetSymbolAddress((void**)&wth_l, g_wth_l);
    cudaGetSymbolAddress((void**)&wph_h, g_wph_h);cudaGetSymbolAddress((void**)&wph_l, g_wph_l);
    cudaGetSymbolAddress((void**)&wg_h, g_wg_h);  cudaGetSymbolAddress((void**)&wg_l, g_wg_l);
    cudaGetSymbolAddress((void**)&wo_h, g_wo_h);  cudaGetSymbolAddress((void**)&wo_l, g_wo_l);
    cudaGetSymbolAddress((void**)&scl, g_scl);    cudaGetSymbolAddress((void**)&off, g_off);

    cudaFuncSetAttribute(mma_gemm<1,2,0,0>, cudaFuncAttributeMaxDynamicSharedMemorySize, SMEMD0);
    cudaFuncSetAttribute(mma_gemm<2,1,0,0>, cudaFuncAttributeMaxDynamicSharedMemorySize, SMEMD0);
    cudaFuncSetAttribute(mma_gemm<0,0,0,0>, cudaFuncAttributeMaxDynamicSharedMemorySize, SMEMD0);
    cudaFuncSetAttribute(mma_gemm<1,0,0,1>, cudaFuncAttributeMaxDynamicSharedMemorySize, SMEMD1);
    cudaFuncSetAttribute(mma_gemm<0,0,1,0>, cudaFuncAttributeMaxDynamicSharedMemorySize, SMEMD0);

    // launch 0
    affine_kernel<<<(Cc + 255) / 256, 256>>>(b_out, bn_gm, bn_bt, bn_mn, bn_vr, scl, off);

    // launch 1: all 4 weight splits
    wsplit4<<<dim3((Ee * Cc + 255) / 256, 4), 256>>>(
        w_theta, w_phi, w_g, w_out,
        wth_h, wth_l, wph_h, wph_l, wg_h, wg_l, wo_h, wo_l);

    // launch 2
    xpose_split<<<dim3(NN / 32, Cc / 32, Bb), dim3(32, 8)>>>(x, xT_h, xT_l);

    // launch 3 (ncu capture lands here): thetaT[n,e] = sum_c xT[n,c] w_theta[e,c] + b_theta[e]
    mma_gemm<1,2,0,0><<<dim3(Ee / 128, NN / 128, Bb), 256, SMEMD0>>>(
        xT_h, xT_l, (long)NN * Cc, NN,
        wth_h, wth_l, 0L, Ee, Cc,
        nullptr, th_h, th_l, (long)NN * Ee, Ee, NN, Ee,
        b_theta, nullptr, nullptr, nullptr, 0L);

    // launch 4
    pool_xpose_split<<<dim3(MM / 32, Cc / 32, Bb), dim3(32, 8)>>>(x, xsT_h, xsT_l);

    // launch 5: phiT[m,e] = sum_c xsT[m,c] w_phi[e,c] + b_phi[e]
    mma_gemm<1,2,0,0><<<dim3(Ee / 128, (MM + 127) / 128, Bb), 256, SMEMD0>>>(
        xsT_h, xsT_l, (long)MM * Cc, MM,
        wph_h, wph_l, 0L, Ee, Cc,
        nullptr, ph_h, ph_l, (long)MM * Ee, Ee, MM, Ee,
        b_phi, nullptr, nullptr, nullptr, 0L);

    // launch 6: g[e,m] = sum_c w_g[e,c] xsT[m,c] + b_g[e]   -> fp16 hi/lo
    mma_gemm<2,1,0,0><<<dim3((MM + 127) / 128, Ee / 128, Bb), 256, SMEMD0>>>(
        wg_h, wg_l, 0L, Ee,
        xsT_h, xsT_l, (long)MM * Cc, MM, Cc,
        nullptr, gg_h, gg_l, (long)Ee * MM, MM, Ee, MM,
        b_g, nullptr, nullptr, nullptr, 0L);

    // launch 7: scores[n,m] = sum_e thetaT[n,e] phiT[m,e]
    mma_gemm<0,0,0,0><<<dim3((MM + 127) / 128, NN / 128, Bb), 256, SMEMD0>>>(
        th_h, th_l, (long)NN * Ee, NN,
        ph_h, ph_l, (long)MM * Ee, MM, Ee,
        sc, nullptr, nullptr, (long)NN * MM, MM, NN, MM,
        nullptr, nullptr, nullptr, nullptr, 0L);

    // launch 8: softmax -> single fp16 P
    softmax_fp16<<<Bb * NN, 256>>>(sc, (__half*)p_h);

    // launch 9: yT[n,e] = sum_m P[n,m] g[e,m]   (fp16 2-pass)
    mma_gemm<1,0,0,1><<<dim3(Ee / 128, NN / 128, Bb), 256, SMEMD1>>>(
        p_h, p_h, (long)NN * MM, NN,
        gg_h, gg_l, (long)Ee * MM, Ee, MM,
        nullptr, y_h, y_l, (long)NN * Ee, Ee, NN, Ee,
        nullptr, nullptr, nullptr, nullptr, 0L);

    // launch 10: out[c,n] = BN(sum_e w_out[c,e] yT[n,e]) + x[c,n]
    mma_gemm<0,0,1,0><<<dim3(NN / 128, Cc / 128, Bb), 256, SMEMD0>>>(
        wo_h, wo_l, 0L, Cc,
        y_h, y_l, (long)NN * Ee, NN, Ee,
        out, nullptr, nullptr, (long)Cc * NN, NN, Cc, NN,
        nullptr, scl, off, x, (long)Cc * NN);
}

// round 16
// speedup vs baseline: 2.3950x; 1.0524x over previous
#include <cuda_runtime.h>
#include <cuda_bf16.h>
#include <cuda_fp16.h>
#include <cstdint>

#define Bb 8
#define Cc 1024
#define Tt 8
#define Ee 512
#define NN 6272
#define MM 1568
#define EPSV 1e-5f

typedef unsigned int u32;
typedef unsigned long long u64;
typedef __nv_bfloat16 bf16;

// ------------------- device scratch -------------------
__device__ bf16 g_xT_h[(long)Bb*NN*Cc], g_xT_l[(long)Bb*NN*Cc];     // x^T [B,N,C]
__device__ bf16 g_xsT_h[(long)Bb*MM*Cc], g_xsT_l[(long)Bb*MM*Cc];   // xsub^T [B,M,C]
__device__ bf16 g_th_h[(long)Bb*NN*Ee], g_th_l[(long)Bb*NN*Ee];     // theta^T [B,N,E]
__device__ bf16 g_ph_h[(long)Bb*MM*Ee], g_ph_l[(long)Bb*MM*Ee];     // phi^T [B,M,E]
__device__ bf16 g_g_h[(long)Bb*Ee*MM], g_g_l[(long)Bb*Ee*MM];       // g [B,E,M] (fp16 bits)
__device__ float g_sc[(long)Bb*NN*MM];                              // scores [B,N,M]
__device__ bf16 g_p_h[(long)Bb*NN*MM];                              // P [B,N,M] fp16 bits
__device__ bf16 g_y_h[(long)Bb*NN*Ee];                              // y^T [B,N,E] fp16 bits (single)
__device__ bf16 g_wth_h[Ee*Cc], g_wth_l[Ee*Cc];
__device__ bf16 g_wph_h[Ee*Cc], g_wph_l[Ee*Cc];
__device__ bf16 g_wg_h [Ee*Cc], g_wg_l [Ee*Cc];
__device__ bf16 g_wo_h [Cc*Ee], g_wo_l [Cc*Ee];                     // fp16 bits
__device__ float g_scl[Cc], g_off[Cc];

// ------------------- helpers -------------------
__device__ __forceinline__ u32 s2u(const void* p){
    u32 a; asm("{ .reg .u64 t; cvta.to.shared.u64 t, %1; cvt.u32.u64 %0, t; }" : "=r"(a) : "l"(p)); return a;
}
__device__ __forceinline__ void cpa16(u32 dst, const void* src, int valid){
    int sz = valid ? 16 : 0;
    asm volatile("cp.async.cg.shared.global [%0], [%1], 16, %2;" :: "r"(dst), "l"(src), "r"(sz));
}
#define CP_COMMIT() asm volatile("cp.async.commit_group;" ::: "memory")
#define CP_WAIT1()  asm volatile("cp.async.wait_group 1;" ::: "memory")

__device__ __forceinline__ void ldm4(u32* r, u32 addr){
    asm volatile("ldmatrix.sync.aligned.m8n8.x4.shared.b16 {%0,%1,%2,%3}, [%4];"
        : "=r"(r[0]), "=r"(r[1]), "=r"(r[2]), "=r"(r[3]) : "r"(addr));
}
// FP16V: 0 = bf16 mma, 1 = fp16 mma
template<int FP16V>
__device__ __forceinline__ void mmaT(float* c, const u32* a, const u32* b){
    if (FP16V == 0){
        asm volatile("mma.sync.aligned.m16n8k16.row.col.f32.bf16.bf16.f32 "
            "{%0,%1,%2,%3}, {%4,%5,%6,%7}, {%8,%9}, {%0,%1,%2,%3};"
            : "+f"(c[0]), "+f"(c[1]), "+f"(c[2]), "+f"(c[3])
            : "r"(a[0]), "r"(a[1]), "r"(a[2]), "r"(a[3]), "r"(b[0]), "r"(b[1]));
    } else {
        asm volatile("mma.sync.aligned.m16n8k16.row.col.f32.f16.f16.f32 "
            "{%0,%1,%2,%3}, {%4,%5,%6,%7}, {%8,%9}, {%0,%1,%2,%3};"
            : "+f"(c[0]), "+f"(c[1]), "+f"(c[2]), "+f"(c[3])
            : "r"(a[0]), "r"(a[1]), "r"(a[2]), "r"(a[3]), "r"(b[0]), "r"(b[1]));
    }
}

// smem geometry: dense 64B rows (128 rows x 32 halfword), granule-swizzled:
//   physical 16B-granule = logical ^ ((row>>1)&3)
#define TILEB  (128*64)        // 8192 B per 128x32 tile
#define NSTG   3
#define SMEMD0 (NSTG*4*TILEB)  // 3-pass: Ah,Al,Bh,Bl = 98304 B
#define SMEMD1 (NSTG*3*TILEB)  // 2-pass: 3 tiles     = 73728 B

// ------------------- generic split warp-MMA GEMM -------------------
// C[z][o][n] = sum_k A[z][o][k] * B[z][n][k]   (both K-major)
// PREC 0: bf16 hi/lo x bf16 hi/lo, 3 passes.
// PREC 1: A single fp16, B fp16 hi/lo, 2 passes.
// PREC 2: A fp16 hi/lo, B single fp16, 2 passes.
// OUTM: 0 fp32 out, 1 bf16 hi/lo out, 2 fp16 hi/lo out, 3 fp16 single out
// BIASM: 0 none, 1 per-row bias[o], 2 per-col bias[n]
// BNM: 1 = v*scl[o]+off[o]+resid[z][o][n]
template<int OUTM, int BIASM, int BNM, int PREC>
__global__ void __launch_bounds__(256, 2)
mma_gemm(const bf16* __restrict__ Ah, const bf16* __restrict__ Al, long sAz, int Arows,
         const bf16* __restrict__ Bh, const bf16* __restrict__ Bl, long sBz, int Brows,
         int K,
         float* __restrict__ Cf, bf16* __restrict__ Ch, bf16* __restrict__ Cl,
         long sCz, int ldC, int Crows, int Ccols,
         const float* __restrict__ bias, const float* __restrict__ scl,
         const float* __restrict__ off, const float* __restrict__ resid, long sRz)
{
    extern __shared__ char sm[];
    constexpr int NT = (PREC == 0) ? 4 : 3;        // tiles per stage
    constexpr int STAGEB = NT * TILEB;
    const int t   = threadIdx.x;
    const int wid = t >> 5, lid = t & 31;
    const int o0  = blockIdx.y * 128, n0 = blockIdx.x * 128;
    const int z   = blockIdx.z;
    const int wm  = wid & 3, wn = wid >> 2;   // warp tile 32x64

    const bf16* Ahz = Ah + (long)z * sAz;
    const bf16* Alz = Al + (long)z * sAz;
    const bf16* Bhz = Bh + (long)z * sBz;
    const bf16* Blz = Bl + (long)z * sBz;

    const u32 smb = s2u(sm);

    // per-thread cp.async indexing: 512 16B-granules per 128x32 tile, 2 per thread
    const int id0 = t, id1 = t + 256;
    const int r0 = id0 >> 2, ch0 = id0 & 3;
    const int r1 = id1 >> 2, ch1 = id1 & 3;
    const int ar0 = o0 + r0, ar1 = o0 + r1;
    const int br0 = n0 + r0, br1 = n0 + r1;
    const int av0 = ar0 < Arows, av1 = ar1 < Arows;
    const int bv0 = br0 < Brows, bv1 = br1 < Brows;
    const long aoff0 = (long)(av0 ? ar0 : 0) * K + ch0 * 8;
    const long aoff1 = (long)(av1 ? ar1 : 0) * K + ch1 * 8;
    const long boff0 = (long)(bv0 ? br0 : 0) * K + ch0 * 8;
    const long boff1 = (long)(bv1 ? br1 : 0) * K + ch1 * 8;
    // swizzled smem destinations
    const u32 dst0 = (u32)(r0 * 64 + (ch0 ^ ((r0 >> 1) & 3)) * 16);
    const u32 dst1 = (u32)(r1 * 64 + (ch1 ^ ((r1 >> 1) & 3)) * 16);

    auto load_stage = [&](int st, int kb){
        u32 b = smb + st * STAGEB;
        long ko = (long)kb * 32;
        if (PREC == 0){
            cpa16(b + dst0,             Ahz + aoff0 + ko, av0);
            cpa16(b + dst1,             Ahz + aoff1 + ko, av1);
            cpa16(b + TILEB   + dst0,   Alz + aoff0 + ko, av0);
            cpa16(b + TILEB   + dst1,   Alz + aoff1 + ko, av1);
            cpa16(b + 2*TILEB + dst0,   Bhz + boff0 + ko, bv0);
            cpa16(b + 2*TILEB + dst1,   Bhz + boff1 + ko, bv1);
            cpa16(b + 3*TILEB + dst0,   Blz + boff0 + ko, bv0);
            cpa16(b + 3*TILEB + dst1,   Blz + boff1 + ko, bv1);
        } else if (PREC == 1){
            cpa16(b + dst0,             Ahz + aoff0 + ko, av0);
            cpa16(b + dst1,             Ahz + aoff1 + ko, av1);
            cpa16(b + TILEB   + dst0,   Bhz + boff0 + ko, bv0);
            cpa16(b + TILEB   + dst1,   Bhz + boff1 + ko, bv1);
            cpa16(b + 2*TILEB + dst0,   Blz + boff0 + ko, bv0);
            cpa16(b + 2*TILEB + dst1,   Blz + boff1 + ko, bv1);
        } else {
            cpa16(b + dst0,             Ahz + aoff0 + ko, av0);
            cpa16(b + dst1,             Ahz + aoff1 + ko, av1);
            cpa16(b + TILEB   + dst0,   Alz + aoff0 + ko, av0);
            cpa16(b + TILEB   + dst1,   Alz + aoff1 + ko, av1);
            cpa16(b + 2*TILEB + dst0,   Bhz + boff0 + ko, bv0);
            cpa16(b + 2*TILEB + dst1,   Bhz + boff1 + ko, bv1);
        }
        CP_COMMIT();
    };

    // ldmatrix lane geometry: row base + per-row swizzle key
    u32 arowb[2], aswz[2], browb[4], bswz[4];
#pragma unroll
    for (int i = 0; i < 2; i++){
        int r = wm*32 + i*16 + (lid & 15);
        arowb[i] = (u32)(r * 64);
        aswz[i]  = (u32)((r >> 1) & 3);
    }
    const u32 glA = (u32)(lid >> 4);        // logical granule 0/1 (ks adds 2)
#pragma unroll
    for (int j = 0; j < 4; j++){
        int r = wn*64 + j*16 + (lid & 7) + ((lid & 16) >> 1);
        browb[j] = (u32)(r * 64);
        bswz[j]  = (u32)((r >> 1) & 3);
    }
    const u32 glB = (u32)((lid >> 3) & 1);

    float acc[2][8][4];
#pragma unroll
    for (int i = 0; i < 2; i++)
#pragma unroll
        for (int j = 0; j < 8; j++)
#pragma unroll
            for (int k = 0; k < 4; k++) acc[i][j][k] = 0.f;

    const int nkb = K >> 5;
    // prologue: fill stages 0 and 1
    load_stage(0, 0);
    load_stage(1, 1);

    int cur = 0;    // stage holding kb
    int nxt = 2;    // stage to fill with kb+2
    for (int kb = 0; kb < nkb; kb++){
        CP_WAIT1();          // own group kb landed (1 group may remain in flight)
        __syncthreads();     // ALL threads passed their wait -> group kb globally visible;
                             // also: everyone done reading stage `nxt` (= stage of kb-1)
        if (kb + 2 < nkb) load_stage(nxt, kb + 2);
        else              CP_COMMIT();   // empty group keeps wait_group pacing

        const u32 base = smb + cur * STAGEB;
#pragma unroll
        for (int ks = 0; ks < 2; ks++){
            const u32 kg = (u32)(ks << 1);
            if (PREC == 0){
                u32 ah[2][4], al[2][4], bh[4][4], bl[4][4];
#pragma unroll
                for (int i = 0; i < 2; i++){
                    u32 ao = arowb[i] + (((glA | kg) ^ aswz[i]) << 4);
                    ldm4(ah[i], base + ao);
                    ldm4(al[i], base + TILEB + ao);
                }
#pragma unroll
                for (int j = 0; j < 4; j++){
                    u32 bo = browb[j] + (((glB | kg) ^ bswz[j]) << 4);
                    ldm4(bh[j], base + 2*TILEB + bo);
                    ldm4(bl[j], base + 3*TILEB + bo);
                }
#pragma unroll
                for (int i = 0; i < 2; i++){
#pragma unroll
                    for (int j8 = 0; j8 < 8; j8++){
                        const u32* bhp = &bh[j8 >> 1][(j8 & 1) * 2];
                        const u32* blp = &bl[j8 >> 1][(j8 & 1) * 2];
                        mmaT<0>(acc[i][j8], ah[i], bhp);   // hi*hi
                        mmaT<0>(acc[i][j8], ah[i], blp);   // hi*lo
                        mmaT<0>(acc[i][j8], al[i], bhp);   // lo*hi
                    }
                }
            } else if (PREC == 1){
                u32 a[2][4], bh[4][4], bl[4][4];
#pragma unroll
                for (int i = 0; i < 2; i++){
                    u32 ao = arowb[i] + (((glA | kg) ^ aswz[i]) << 4);
                    ldm4(a[i], base + ao);
                }
#pragma unroll
                for (int j = 0; j < 4; j++){
                    u32 bo = browb[j] + (((glB | kg) ^ bswz[j]) << 4);
                    ldm4(bh[j], base + TILEB + bo);
                    ldm4(bl[j], base + 2*TILEB + bo);
                }
#pragma unroll
                for (int i = 0; i < 2; i++){
#pragma unroll
                    for (int j8 = 0; j8 < 8; j8++){
                        const u32* bhp = &bh[j8 >> 1][(j8 & 1) * 2];
                        const u32* blp = &bl[j8 >> 1][(j8 & 1) * 2];
                        mmaT<1>(acc[i][j8], a[i], bhp);    // A*Bh
                        mmaT<1>(acc[i][j8], a[i], blp);    // A*Bl
                    }
                }
            } else {
                u32 ah[2][4], al[2][4], b4[4][4];
#pragma unroll
                for (int i = 0; i < 2; i++){
                    u32 ao = arowb[i] + (((glA | kg) ^ aswz[i]) << 4);
                    ldm4(ah[i], base + ao);
                    ldm4(al[i], base + TILEB + ao);
                }
#pragma unroll
                for (int j = 0; j < 4; j++){
                    u32 bo = browb[j] + (((glB | kg) ^ bswz[j]) << 4);
                    ldm4(b4[j], base + 2*TILEB + bo);
                }
#pragma unroll
                for (int i = 0; i < 2; i++){
#pragma unroll
                    for (int j8 = 0; j8 < 8; j8++){
                        const u32* bp = &b4[j8 >> 1][(j8 & 1) * 2];
                        mmaT<1>(acc[i][j8], ah[i], bp);    // Ah*B
                        mmaT<1>(acc[i][j8], al[i], bp);    // Al*B
                    }
                }
            }
        }
        cur = (cur == NSTG - 1) ? 0 : cur + 1;
        nxt = (nxt == NSTG - 1) ? 0 : nxt + 1;
    }

    // ------------------- epilogue -------------------
    const int q = lid >> 2, tq = lid & 3;
    const int rbase = o0 + wm * 32;
    const int cbase = n0 + wn * 64;
#pragma unroll
    for (int i = 0; i < 2; i++){
#pragma unroll
        for (int half = 0; half < 2; half++){
            const int row = rbase + i * 16 + q + half * 8;
            if (row >= Crows) continue;
            float brow = 0.f, sc_r = 0.f, of_r = 0.f;
            if (BIASM == 1) brow = bias[row];
            if (BNM == 1){ sc_r = scl[row]; of_r = off[row]; }
            const float* rrow = (BNM == 1) ? (resid + (long)z * sRz + (long)row * ldC) : nullptr;
            float* cfrow = (OUTM == 0) ? (Cf + (long)z * sCz + (long)row * ldC) : nullptr;
            bf16* chrow  = (OUTM != 0) ? (Ch + (long)z * sCz + (long)row * ldC) : nullptr;
            bf16* clrow  = (OUTM == 1 || OUTM == 2) ? (Cl + (long)z * sCz + (long)row * ldC) : nullptr;
#pragma unroll
            for (int j8 = 0; j8 < 8; j8++){
                const int col = cbase + j8 * 8 + tq * 2;
                if (col >= Ccols) continue;
                float v0 = acc[i][j8][half * 2 + 0];
                float v1 = acc[i][j8][half * 2 + 1];
                if (BIASM == 1){ v0 += brow; v1 += brow; }
                if (BIASM == 2){ v0 += bias[col]; v1 += bias[col + 1]; }
                if (BNM == 1){
                    v0 = v0 * sc_r + of_r + rrow[col];
                    v1 = v1 * sc_r + of_r + rrow[col + 1];
                }
                if (OUTM == 0){
                    *(float2*)(cfrow + col) = make_float2(v0, v1);
                } else if (OUTM == 1){
                    bf16 h0 = __float2bfloat16(v0);
                    bf16 h1 = __float2bfloat16(v1);
                    bf16 l0 = __float2bfloat16(v0 - __bfloat162float(h0));
                    bf16 l1 = __float2bfloat16(v1 - __bfloat162float(h1));
                    u32 hp = ((u32)__bfloat16_as_ushort(h1) << 16) | __bfloat16_as_ushort(h0);
                    u32 lp = ((u32)__bfloat16_as_ushort(l1) << 16) | __bfloat16_as_ushort(l0);
                    *(u32*)(chrow + col) = hp;
                    *(u32*)(clrow + col) = lp;
                } else if (OUTM == 2){
                    __half h0 = __float2half_rn(v0);
                    __half h1 = __float2half_rn(v1);
                    __half l0 = __float2half_rn(v0 - __half2float(h0));
                    __half l1 = __float2half_rn(v1 - __half2float(h1));
                    u32 hp = ((u32)__half_as_ushort(h1) << 16) | __half_as_ushort(h0);
                    u32 lp = ((u32)__half_as_ushort(l1) << 16) | __half_as_ushort(l0);
                    *(u32*)(chrow + col) = hp;
                    *(u32*)(clrow + col) = lp;
                } else {
                    __half h0 = __float2half_rn(v0);
                    __half h1 = __float2half_rn(v1);
                    u32 hp = ((u32)__half_as_ushort(h1) << 16) | __half_as_ushort(h0);
                    *(u32*)(chrow + col) = hp;
                }
            }
        }
    }
}

// ------------------- conversion kernels -------------------
// split 4 weight matrices; w_out (idx 3) splits to fp16, others bf16
__global__ void wsplit4(const float* __restrict__ w0, const float* __restrict__ w1,
                        const float* __restrict__ w2, const float* __restrict__ w3,
                        bf16* __restrict__ h0, bf16* __restrict__ l0,
                        bf16* __restrict__ h1, bf16* __restrict__ l1,
                        bf16* __restrict__ h2, bf16* __restrict__ l2,
                        bf16* __restrict__ h3, bf16* __restrict__ l3){
    const long n = (long)Ee * Cc;
    long i = (long)blockIdx.x * blockDim.x + threadIdx.x;
    if (i >= n) return;
    const float* in; bf16 *hi, *lo;
    switch (blockIdx.y){
        case 0: in = w0; hi = h0; lo = l0; break;
        case 1: in = w1; hi = h1; lo = l1; break;
        case 2: in = w2; hi = h2; lo = l2; break;
        default:in = w3; hi = h3; lo = l3; break;
    }
    float v = in[i];
    if (blockIdx.y == 3){
        __half h = __float2half_rn(v);
        ((__half*)hi)[i] = h;
        ((__half*)lo)[i] = __float2half_rn(v - __half2float(h));
    } else {
        bf16 h = __float2bfloat16(v);
        hi[i] = h;
        lo[i] = __float2bfloat16(v - __bfloat162float(h));
    }
}

// x [B,C,N] -> xT hi/lo [B,N,C]
__global__ void xpose_split(const float* __restrict__ x,
                            bf16* __restrict__ oh, bf16* __restrict__ ol){
    __shared__ float tile[32][33];
    const int tx = threadIdx.x, ty = threadIdx.y;
    const int n0 = blockIdx.x * 32, c0 = blockIdx.y * 32, z = blockIdx.z;
    const float* xz = x + (long)z * Cc * NN;
#pragma unroll
    for (int j = 0; j < 4; j++){
        int c = c0 + ty + j * 8;
        tile[ty + j * 8][tx] = xz[(long)c * NN + n0 + tx];
    }
    __syncthreads();
    bf16* ohz = oh + (long)z * NN * Cc;
    bf16* olz = ol + (long)z * NN * Cc;
#pragma unroll
    for (int j = 0; j < 4; j++){
        int n = n0 + ty + j * 8;
        float v = tile[tx][ty + j * 8];
        bf16 h = __float2bfloat16(v);
        long idx = (long)n * Cc + c0 + tx;
        ohz[idx] = h;
        olz[idx] = __float2bfloat16(v - __bfloat162float(h));
    }
}

// maxpool (1,2,2) + transpose + split: x [B,C,T,28,28] -> xsubT hi/lo [B,M,C]
__global__ void pool_xpose_split(const float* __restrict__ x,
                                 bf16* __restrict__ oh, bf16* __restrict__ ol){
    __shared__ float tile[32][33];
    const int tx = threadIdx.x, ty = threadIdx.y;
    const int m0 = blockIdx.x * 32, c0 = blockIdx.y * 32, z = blockIdx.z;
    const int m = m0 + tx;
    const int t_ = m / 196, r = m % 196, h2 = r / 14, w2 = r % 14;
#pragma unroll
    for (int j = 0; j < 4; j++){
        int c = c0 + ty + j * 8;
        const float* p = x + ((((long)z * Cc + c) * Tt + t_) * 28 + h2 * 2) * 28 + w2 * 2;
        float v = fmaxf(fmaxf(p[0], p[1]), fmaxf(p[28], p[29]));
        tile[ty + j * 8][tx] = v;
    }
    __syncthreads();
    bf16* ohz = oh + (long)z * MM * Cc;
    bf16* olz = ol + (long)z * MM * Cc;
#pragma unroll
    for (int j = 0; j < 4; j++){
        int mw = m0 + ty + j * 8;
        float v = tile[tx][ty + j * 8];
        bf16 h = __float2bfloat16(v);
        long idx = (long)mw * Cc + c0 + tx;
        ohz[idx] = h;
        olz[idx] = __float2bfloat16(v - __bfloat162float(h));
    }
}

// row softmax over 1568 keys -> single fp16 P
__global__ void softmax_fp16(const float* __restrict__ S, __half* __restrict__ ph){
    const long row = blockIdx.x;
    const float* p = S + row * MM;
    const int t = threadIdx.x;
    float v[7];
    float lm = -3.4e38f;
#pragma unroll
    for (int it = 0; it < 7; it++){
        int idx = t + it * 256;
        v[it] = (idx < MM) ? p[idx] : -3.4e38f;
        lm = fmaxf(lm, v[it]);
    }
    __shared__ float red[256];
    red[t] = lm; __syncthreads();
    for (int s = 128; s > 0; s >>= 1){ if (t < s) red[t] = fmaxf(red[t], red[t + s]); __syncthreads(); }
    float m = red[0];
    __syncthreads();
    float ls = 0.f;
#pragma unroll
    for (int it = 0; it < 7; it++){
        int idx = t + it * 256;
        if (idx < MM){ float e = __expf(v[it] - m); v[it] = e; ls += e; }
    }
    red[t] = ls; __syncthreads();
    for (int s = 128; s > 0; s >>= 1){ if (t < s) red[t] += red[t + s]; __syncthreads(); }
    float inv = 1.f / red[0];
    __half* phr = ph + row * MM;
#pragma unroll
    for (int it = 0; it < 7; it++){
        int idx = t + it * 256;
        if (idx < MM) phr[idx] = __float2half_rn(v[it] * inv);
    }
}

__global__ void affine_kernel(const float* __restrict__ bo, const float* __restrict__ gm,
                              const float* __restrict__ bt, const float* __restrict__ mn,
                              const float* __restrict__ vr,
                              float* __restrict__ scl, float* __restrict__ off){
    int c = blockIdx.x * blockDim.x + threadIdx.x;
    if (c < Cc){
        float s = gm[c] * rsqrtf(vr[c] + EPSV);
        scl[c] = s;
        off[c] = (bo[c] - mn[c]) * s + bt[c];
    }
}

// ------------------- launch -------------------
extern "C" void kernel_launch(void* const* d_in, const int* in_sizes, int n_in,
                              void* d_out, int out_size){
    const float* x       = (const float*)d_in[0];
    const float* w_theta = (const float*)d_in[1];
    const float* b_theta = (const float*)d_in[2];
    const float* w_phi   = (const float*)d_in[3];
    const float* b_phi   = (const float*)d_in[4];
    const float* w_g     = (const float*)d_in[5];
    const float* b_g     = (const float*)d_in[6];
    const float* w_out   = (const float*)d_in[7];
    const float* b_out   = (const float*)d_in[8];
    const float* bn_gm   = (const float*)d_in[9];
    const float* bn_bt   = (const float*)d_in[10];
    const float* bn_mn   = (const float*)d_in[11];
    const float* bn_vr   = (const float*)d_in[12];
    float* out = (float*)d_out;

    bf16 *xT_h, *xT_l, *xsT_h, *xsT_l, *th_h, *th_l, *ph_h, *ph_l;
    bf16 *gg_h, *gg_l, *p_h, *y_h;
    bf16 *wth_h, *wth_l, *wph_h, *wph_l, *wg_h, *wg_l, *wo_h, *wo_l;
    float *sc, *scl, *off;
    cudaGetSymbolAddress((void**)&xT_h, g_xT_h);  cudaGetSymbolAddress((void**)&xT_l, g_xT_l);
    cudaGetSymbolAddress((void**)&xsT_h, g_xsT_h);cudaGetSymbolAddress((void**)&xsT_l, g_xsT_l);
    cudaGetSymbolAddress((void**)&th_h, g_th_h);  cudaGetSymbolAddress((void**)&th_l, g_th_l);
    cudaGetSymbolAddress((void**)&ph_h, g_ph_h);  cudaGetSymbolAddress((void**)&ph_l, g_ph_l);
    cudaGetSymbolAddress((void**)&gg_h, g_g_h);   cudaGetSymbolAddress((void**)&gg_l, g_g_l);
    cudaGetSymbolAddress((void**)&sc, g_sc);
    cudaGetSymbolAddress((void**)&p_h, g_p_h);
    cudaGetSymbolAddress((void**)&y_h, g_y_h);
    cudaGetSymbolAddress((void**)&wth_h, g_wth_h);cudaGetSymbolAddress((void**)&wth_l, g_wth_l);
    cudaGetSymbolAddress((void**)&wph_h, g_wph_h);cudaGetSymbolAddress((void**)&wph_l, g_wph_l);
    cudaGetSymbolAddress((void**)&wg_h, g_wg_h);  cudaGetSymbolAddress((void**)&wg_l, g_wg_l);
    cudaGetSymbolAddress((void**)&wo_h, g_wo_h);  cudaGetSymbolAddress((void**)&wo_l, g_wo_l);
    cudaGetSymbolAddress((void**)&scl, g_scl);    cudaGetSymbolAddress((void**)&off, g_off);

    cudaFuncSetAttribute(mma_gemm<1,2,0,0>, cudaFuncAttributeMaxDynamicSharedMemorySize, SMEMD0);
    cudaFuncSetAttribute(mma_gemm<2,1,0,0>, cudaFuncAttributeMaxDynamicSharedMemorySize, SMEMD0);
    cudaFuncSetAttribute(mma_gemm<0,0,0,0>, cudaFuncAttributeMaxDynamicSharedMemorySize, SMEMD0);
    cudaFuncSetAttribute(mma_gemm<3,0,0,1>, cudaFuncAttributeMaxDynamicSharedMemorySize, SMEMD1);
    cudaFuncSetAttribute(mma_gemm<0,0,1,2>, cudaFuncAttributeMaxDynamicSharedMemorySize, SMEMD1);

    // launch 0
    affine_kernel<<<(Cc + 255) / 256, 256>>>(b_out, bn_gm, bn_bt, bn_mn, bn_vr, scl, off);

    // launch 1: all 4 weight splits (w_out -> fp16)
    wsplit4<<<dim3((Ee * Cc + 255) / 256, 4), 256>>>(
        w_theta, w_phi, w_g, w_out,
        wth_h, wth_l, wph_h, wph_l, wg_h, wg_l, wo_h, wo_l);

    // launch 2
    xpose_split<<<dim3(NN / 32, Cc / 32, Bb), dim3(32, 8)>>>(x, xT_h, xT_l);

    // launch 3 (ncu capture lands here): thetaT[n,e] = sum_c xT[n,c] w_theta[e,c] + b_theta[e]
    mma_gemm<1,2,0,0><<<dim3(Ee / 128, NN / 128, Bb), 256, SMEMD0>>>(
        xT_h, xT_l, (long)NN * Cc, NN,
        wth_h, wth_l, 0L, Ee, Cc,
        nullptr, th_h, th_l, (long)NN * Ee, Ee, NN, Ee,
        b_theta, nullptr, nullptr, nullptr, 0L);

    // launch 4
    pool_xpose_split<<<dim3(MM / 32, Cc / 32, Bb), dim3(32, 8)>>>(x, xsT_h, xsT_l);

    // launch 5: phiT[m,e] = sum_c xsT[m,c] w_phi[e,c] + b_phi[e]
    mma_gemm<1,2,0,0><<<dim3(Ee / 128, (MM + 127) / 128, Bb), 256, SMEMD0>>>(
        xsT_h, xsT_l, (long)MM * Cc, MM,
        wph_h, wph_l, 0L, Ee, Cc,
        nullptr, ph_h, ph_l, (long)MM * Ee, Ee, MM, Ee,
        b_phi, nullptr, nullptr, nullptr, 0L);

    // launch 6: g[e,m] = sum_c w_g[e,c] xsT[m,c] + b_g[e]   -> fp16 hi/lo
    mma_gemm<2,1,0,0><<<dim3((MM + 127) / 128, Ee / 128, Bb), 256, SMEMD0>>>(
        wg_h, wg_l, 0L, Ee,
        xsT_h, xsT_l, (long)MM * Cc, MM, Cc,
        nullptr, gg_h, gg_l, (long)Ee * MM, MM, Ee, MM,
        b_g, nullptr, nullptr, nullptr, 0L);

    // launch 7: scores[n,m] = sum_e thetaT[n,e] phiT[m,e]
    mma_gemm<0,0,0,0><<<dim3((MM + 127) / 128, NN / 128, Bb), 256, SMEMD0>>>(
        th_h, th_l, (long)NN * Ee, NN,
        ph_h, ph_l, (long)MM * Ee, MM, Ee,
        sc, nullptr, nullptr, (long)NN * MM, MM, NN, MM,
        nullptr, nullptr, nullptr, nullptr, 0L);

    // launch 8: softmax -> single fp16 P
    softmax_fp16<<<Bb * NN, 256>>>(sc, (__half*)p_h);

    // launch 9: yT[n,e] = sum_m P[n,m] g[e,m]   (fp16 2-pass, single fp16 out)
    mma_gemm<3,0,0,1><<<dim3(Ee / 128, NN / 128, Bb), 256, SMEMD1>>>(
        p_h, p_h, (long)NN * MM, NN,
        gg_h, gg_l, (long)Ee * MM, Ee, MM,
        nullptr, y_h, nullptr, (long)NN * Ee, Ee, NN, Ee,
        nullptr, nullptr, nullptr, nullptr, 0L);

    // launch 10: out[c,n] = BN(sum_e w_out[c,e] yT[n,e]) + x[c,n]   (fp16 2-pass)
    mma_gemm<0,0,1,2><<<dim3(NN / 128, Cc / 128, Bb), 256, SMEMD1>>>(
        wo_h, wo_l, 0L, Cc,
        y_h, nullptr, (long)NN * Ee, NN, Ee,
        out, nullptr, nullptr, (long)Cc * NN, NN, Cc, NN,
        nullptr, scl, off, x, (long)Cc * NN);
}

// round 17
// speedup vs baseline: 2.7250x; 1.1378x over previous
#include <cuda_runtime.h>
#include <cuda_bf16.h>
#include <cuda_fp16.h>
#include <cstdint>

#define Bb 8
#define Cc 1024
#define Tt 8
#define Ee 512
#define NN 6272
#define MM 1568
#define EPSV 1e-5f

typedef unsigned int u32;
typedef unsigned long long u64;
typedef __nv_bfloat16 bf16;

// ------------------- device scratch -------------------
__device__ bf16 g_xT_h[(long)Bb*NN*Cc], g_xT_l[(long)Bb*NN*Cc];     // x^T [B,N,C]
__device__ bf16 g_xsT_h[(long)Bb*MM*Cc], g_xsT_l[(long)Bb*MM*Cc];   // xsub^T [B,M,C]
__device__ bf16 g_th_h[(long)Bb*NN*Ee], g_th_l[(long)Bb*NN*Ee];     // theta^T [B,N,E]
__device__ bf16 g_ph_h[(long)Bb*MM*Ee], g_ph_l[(long)Bb*MM*Ee];     // phi^T [B,M,E]
__device__ bf16 g_g_h[(long)Bb*Ee*MM];                              // g [B,E,M] fp16 bits (single)
__device__ float g_sc[(long)Bb*NN*MM];                              // scores [B,N,M]
__device__ bf16 g_p_h[(long)Bb*NN*MM];                              // P [B,N,M] fp16 bits
__device__ bf16 g_y_h[(long)Bb*NN*Ee];                              // y^T [B,N,E] fp16 bits (single)
__device__ bf16 g_wth_h[Ee*Cc], g_wth_l[Ee*Cc];
__device__ bf16 g_wph_h[Ee*Cc], g_wph_l[Ee*Cc];
__device__ bf16 g_wg_h [Ee*Cc], g_wg_l [Ee*Cc];
__device__ bf16 g_wo_h [Cc*Ee];                                     // fp16 bits (single)
__device__ float g_scl[Cc], g_off[Cc];

// ------------------- helpers -------------------
__device__ __forceinline__ u32 s2u(const void* p){
    u32 a; asm("{ .reg .u64 t; cvta.to.shared.u64 t, %1; cvt.u32.u64 %0, t; }" : "=r"(a) : "l"(p)); return a;
}
__device__ __forceinline__ void cpa16(u32 dst, const void* src, int valid){
    int sz = valid ? 16 : 0;
    asm volatile("cp.async.cg.shared.global [%0], [%1], 16, %2;" :: "r"(dst), "l"(src), "r"(sz));
}
#define CP_COMMIT() asm volatile("cp.async.commit_group;" ::: "memory")
#define CP_WAIT1()  asm volatile("cp.async.wait_group 1;" ::: "memory")

__device__ __forceinline__ void ldm4(u32* r, u32 addr){
    asm volatile("ldmatrix.sync.aligned.m8n8.x4.shared.b16 {%0,%1,%2,%3}, [%4];"
        : "=r"(r[0]), "=r"(r[1]), "=r"(r[2]), "=r"(r[3]) : "r"(addr));
}
// FP16V: 0 = bf16 mma, 1 = fp16 mma
template<int FP16V>
__device__ __forceinline__ void mmaT(float* c, const u32* a, const u32* b){
    if (FP16V == 0){
        asm volatile("mma.sync.aligned.m16n8k16.row.col.f32.bf16.bf16.f32 "
            "{%0,%1,%2,%3}, {%4,%5,%6,%7}, {%8,%9}, {%0,%1,%2,%3};"
            : "+f"(c[0]), "+f"(c[1]), "+f"(c[2]), "+f"(c[3])
            : "r"(a[0]), "r"(a[1]), "r"(a[2]), "r"(a[3]), "r"(b[0]), "r"(b[1]));
    } else {
        asm volatile("mma.sync.aligned.m16n8k16.row.col.f32.f16.f16.f32 "
            "{%0,%1,%2,%3}, {%4,%5,%6,%7}, {%8,%9}, {%0,%1,%2,%3};"
            : "+f"(c[0]), "+f"(c[1]), "+f"(c[2]), "+f"(c[3])
            : "r"(a[0]), "r"(a[1]), "r"(a[2]), "r"(a[3]), "r"(b[0]), "r"(b[1]));
    }
}

// smem geometry: dense 64B rows (128 rows x 32 halfword), granule-swizzled:
//   physical 16B-granule = logical ^ ((row>>1)&3)
#define TILEB  (128*64)        // 8192 B per 128x32 tile
#define NSTG   3
#define SMEMD0 (NSTG*4*TILEB)  // 3-pass: Ah,Al,Bh,Bl = 98304 B
#define SMEMD3 (NSTG*2*TILEB)  // 1-pass: A,B         = 49152 B

// ------------------- generic split warp-MMA GEMM -------------------
// C[z][o][n] = sum_k A[z][o][k] * B[z][n][k]   (both K-major)
// PREC 0: bf16 hi/lo x bf16 hi/lo, 3 passes.
// PREC 3: A single fp16 x B single fp16, 1 pass.
// OUTM: 0 fp32 out, 1 bf16 hi/lo out, 3 fp16 single out
// BIASM: 0 none, 1 per-row bias[o], 2 per-col bias[n]
// BNM: 1 = v*scl[o]+off[o]+resid[z][o][n]
template<int OUTM, int BIASM, int BNM, int PREC>
__global__ void __launch_bounds__(256, 2)
mma_gemm(const bf16* __restrict__ Ah, const bf16* __restrict__ Al, long sAz, int Arows,
         const bf16* __restrict__ Bh, const bf16* __restrict__ Bl, long sBz, int Brows,
         int K,
         float* __restrict__ Cf, bf16* __restrict__ Ch, bf16* __restrict__ Cl,
         long sCz, int ldC, int Crows, int Ccols,
         const float* __restrict__ bias, const float* __restrict__ scl,
         const float* __restrict__ off, const float* __restrict__ resid, long sRz)
{
    extern __shared__ char sm[];
    constexpr int NT = (PREC == 0) ? 4 : 2;        // tiles per stage
    constexpr int STAGEB = NT * TILEB;
    const int t   = threadIdx.x;
    const int wid = t >> 5, lid = t & 31;
    const int o0  = blockIdx.y * 128, n0 = blockIdx.x * 128;
    const int z   = blockIdx.z;
    const int wm  = wid & 3, wn = wid >> 2;   // warp tile 32x64

    const bf16* Ahz = Ah + (long)z * sAz;
    const bf16* Alz = Al + (long)z * sAz;
    const bf16* Bhz = Bh + (long)z * sBz;
    const bf16* Blz = Bl + (long)z * sBz;

    const u32 smb = s2u(sm);

    // per-thread cp.async indexing: 512 16B-granules per 128x32 tile, 2 per thread
    const int id0 = t, id1 = t + 256;
    const int r0 = id0 >> 2, ch0 = id0 & 3;
    const int r1 = id1 >> 2, ch1 = id1 & 3;
    const int ar0 = o0 + r0, ar1 = o0 + r1;
    const int br0 = n0 + r0, br1 = n0 + r1;
    const int av0 = ar0 < Arows, av1 = ar1 < Arows;
    const int bv0 = br0 < Brows, bv1 = br1 < Brows;
    const long aoff0 = (long)(av0 ? ar0 : 0) * K + ch0 * 8;
    const long aoff1 = (long)(av1 ? ar1 : 0) * K + ch1 * 8;
    const long boff0 = (long)(bv0 ? br0 : 0) * K + ch0 * 8;
    const long boff1 = (long)(bv1 ? br1 : 0) * K + ch1 * 8;
    // swizzled smem destinations
    const u32 dst0 = (u32)(r0 * 64 + (ch0 ^ ((r0 >> 1) & 3)) * 16);
    const u32 dst1 = (u32)(r1 * 64 + (ch1 ^ ((r1 >> 1) & 3)) * 16);

    auto load_stage = [&](int st, int kb){
        u32 b = smb + st * STAGEB;
        long ko = (long)kb * 32;
        if (PREC == 0){
            cpa16(b + dst0,             Ahz + aoff0 + ko, av0);
            cpa16(b + dst1,             Ahz + aoff1 + ko, av1);
            cpa16(b + TILEB   + dst0,   Alz + aoff0 + ko, av0);
            cpa16(b + TILEB   + dst1,   Alz + aoff1 + ko, av1);
            cpa16(b + 2*TILEB + dst0,   Bhz + boff0 + ko, bv0);
            cpa16(b + 2*TILEB + dst1,   Bhz + boff1 + ko, bv1);
            cpa16(b + 3*TILEB + dst0,   Blz + boff0 + ko, bv0);
            cpa16(b + 3*TILEB + dst1,   Blz + boff1 + ko, bv1);
        } else {
            cpa16(b + dst0,             Ahz + aoff0 + ko, av0);
            cpa16(b + dst1,             Ahz + aoff1 + ko, av1);
            cpa16(b + TILEB   + dst0,   Bhz + boff0 + ko, bv0);
            cpa16(b + TILEB   + dst1,   Bhz + boff1 + ko, bv1);
        }
        CP_COMMIT();
    };

    // ldmatrix lane geometry: row base + per-row swizzle key
    u32 arowb[2], aswz[2], browb[4], bswz[4];
#pragma unroll
    for (int i = 0; i < 2; i++){
        int r = wm*32 + i*16 + (lid & 15);
        arowb[i] = (u32)(r * 64);
        aswz[i]  = (u32)((r >> 1) & 3);
    }
    const u32 glA = (u32)(lid >> 4);        // logical granule 0/1 (ks adds 2)
#pragma unroll
    for (int j = 0; j < 4; j++){
        int r = wn*64 + j*16 + (lid & 7) + ((lid & 16) >> 1);
        browb[j] = (u32)(r * 64);
        bswz[j]  = (u32)((r >> 1) & 3);
    }
    const u32 glB = (u32)((lid >> 3) & 1);

    float acc[2][8][4];
#pragma unroll
    for (int i = 0; i < 2; i++)
#pragma unroll
        for (int j = 0; j < 8; j++)
#pragma unroll
            for (int k = 0; k < 4; k++) acc[i][j][k] = 0.f;

    const int nkb = K >> 5;
    // prologue: fill stages 0 and 1
    load_stage(0, 0);
    load_stage(1, 1);

    int cur = 0;    // stage holding kb
    int nxt = 2;    // stage to fill with kb+2
    for (int kb = 0; kb < nkb; kb++){
        CP_WAIT1();          // own group kb landed (1 group may remain in flight)
        __syncthreads();     // ALL threads passed their wait -> group kb globally visible;
                             // also: everyone done reading stage `nxt` (= stage of kb-1)
        if (kb + 2 < nkb) load_stage(nxt, kb + 2);
        else              CP_COMMIT();   // empty group keeps wait_group pacing

        const u32 base = smb + cur * STAGEB;
#pragma unroll
        for (int ks = 0; ks < 2; ks++){
            const u32 kg = (u32)(ks << 1);
            if (PREC == 0){
                u32 ah[2][4], al[2][4], bh[4][4], bl[4][4];
#pragma unroll
                for (int i = 0; i < 2; i++){
                    u32 ao = arowb[i] + (((glA | kg) ^ aswz[i]) << 4);
                    ldm4(ah[i], base + ao);
                    ldm4(al[i], base + TILEB + ao);
                }
#pragma unroll
                for (int j = 0; j < 4; j++){
                    u32 bo = browb[j] + (((glB | kg) ^ bswz[j]) << 4);
                    ldm4(bh[j], base + 2*TILEB + bo);
                    ldm4(bl[j], base + 3*TILEB + bo);
                }
#pragma unroll
                for (int i = 0; i < 2; i++){
#pragma unroll
                    for (int j8 = 0; j8 < 8; j8++){
                        const u32* bhp = &bh[j8 >> 1][(j8 & 1) * 2];
                        const u32* blp = &bl[j8 >> 1][(j8 & 1) * 2];
                        mmaT<0>(acc[i][j8], ah[i], bhp);   // hi*hi
                        mmaT<0>(acc[i][j8], ah[i], blp);   // hi*lo
                        mmaT<0>(acc[i][j8], al[i], bhp);   // lo*hi
                    }
                }
            } else {
                u32 a[2][4], b4[4][4];
#pragma unroll
                for (int i = 0; i < 2; i++){
                    u32 ao = arowb[i] + (((glA | kg) ^ aswz[i]) << 4);
                    ldm4(a[i], base + ao);
                }
#pragma unroll
                for (int j = 0; j < 4; j++){
                    u32 bo = browb[j] + (((glB | kg) ^ bswz[j]) << 4);
                    ldm4(b4[j], base + TILEB + bo);
                }
#pragma unroll
                for (int i = 0; i < 2; i++){
#pragma unroll
                    for (int j8 = 0; j8 < 8; j8++){
                        const u32* bp = &b4[j8 >> 1][(j8 & 1) * 2];
                        mmaT<1>(acc[i][j8], a[i], bp);     // A*B single pass
                    }
                }
            }
        }
        cur = (cur == NSTG - 1) ? 0 : cur + 1;
        nxt = (nxt == NSTG - 1) ? 0 : nxt + 1;
    }

    // ------------------- epilogue -------------------
    const int q = lid >> 2, tq = lid & 3;
    const int rbase = o0 + wm * 32;
    const int cbase = n0 + wn * 64;
#pragma unroll
    for (int i = 0; i < 2; i++){
#pragma unroll
        for (int half = 0; half < 2; half++){
            const int row = rbase + i * 16 + q + half * 8;
            if (row >= Crows) continue;
            float brow = 0.f, sc_r = 0.f, of_r = 0.f;
            if (BIASM == 1) brow = bias[row];
            if (BNM == 1){ sc_r = scl[row]; of_r = off[row]; }
            const float* rrow = (BNM == 1) ? (resid + (long)z * sRz + (long)row * ldC) : nullptr;
            float* cfrow = (OUTM == 0) ? (Cf + (long)z * sCz + (long)row * ldC) : nullptr;
            bf16* chrow  = (OUTM != 0) ? (Ch + (long)z * sCz + (long)row * ldC) : nullptr;
            bf16* clrow  = (OUTM == 1) ? (Cl + (long)z * sCz + (long)row * ldC) : nullptr;
#pragma unroll
            for (int j8 = 0; j8 < 8; j8++){
                const int col = cbase + j8 * 8 + tq * 2;
                if (col >= Ccols) continue;
                float v0 = acc[i][j8][half * 2 + 0];
                float v1 = acc[i][j8][half * 2 + 1];
                if (BIASM == 1){ v0 += brow; v1 += brow; }
                if (BIASM == 2){ v0 += bias[col]; v1 += bias[col + 1]; }
                if (BNM == 1){
                    v0 = v0 * sc_r + of_r + rrow[col];
                    v1 = v1 * sc_r + of_r + rrow[col + 1];
                }
                if (OUTM == 0){
                    *(float2*)(cfrow + col) = make_float2(v0, v1);
                } else if (OUTM == 1){
                    bf16 h0 = __float2bfloat16(v0);
                    bf16 h1 = __float2bfloat16(v1);
                    bf16 l0 = __float2bfloat16(v0 - __bfloat162float(h0));
                    bf16 l1 = __float2bfloat16(v1 - __bfloat162float(h1));
                    u32 hp = ((u32)__bfloat16_as_ushort(h1) << 16) | __bfloat16_as_ushort(h0);
                    u32 lp = ((u32)__bfloat16_as_ushort(l1) << 16) | __bfloat16_as_ushort(l0);
                    *(u32*)(chrow + col) = hp;
                    *(u32*)(clrow + col) = lp;
                } else {
                    __half h0 = __float2half_rn(v0);
                    __half h1 = __float2half_rn(v1);
                    u32 hp = ((u32)__half_as_ushort(h1) << 16) | __half_as_ushort(h0);
                    *(u32*)(chrow + col) = hp;
                }
            }
        }
    }
}

// ------------------- conversion kernels -------------------
// split 4 weight matrices; w_out (idx 3) -> fp16 single (lo unused)
__global__ void wsplit4(const float* __restrict__ w0, const float* __restrict__ w1,
                        const float* __restrict__ w2, const float* __restrict__ w3,
                        bf16* __restrict__ h0, bf16* __restrict__ l0,
                        bf16* __restrict__ h1, bf16* __restrict__ l1,
                        bf16* __restrict__ h2, bf16* __restrict__ l2,
                        bf16* __restrict__ h3){
    const long n = (long)Ee * Cc;
    long i = (long)blockIdx.x * blockDim.x + threadIdx.x;
    if (i >= n) return;
    if (blockIdx.y == 3){
        ((__half*)h3)[i] = __float2half_rn(w3[i]);
        return;
    }
    const float* in; bf16 *hi, *lo;
    switch (blockIdx.y){
        case 0: in = w0; hi = h0; lo = l0; break;
        case 1: in = w1; hi = h1; lo = l1; break;
        default:in = w2; hi = h2; lo = l2; break;
    }
    float v = in[i];
    bf16 h = __float2bfloat16(v);
    hi[i] = h;
    lo[i] = __float2bfloat16(v - __bfloat162float(h));
}

// x [B,C,N] -> xT hi/lo [B,N,C]
__global__ void xpose_split(const float* __restrict__ x,
                            bf16* __restrict__ oh, bf16* __restrict__ ol){
    __shared__ float tile[32][33];
    const int tx = threadIdx.x, ty = threadIdx.y;
    const int n0 = blockIdx.x * 32, c0 = blockIdx.y * 32, z = blockIdx.z;
    const float* xz = x + (long)z * Cc * NN;
#pragma unroll
    for (int j = 0; j < 4; j++){
        int c = c0 + ty + j * 8;
        tile[ty + j * 8][tx] = xz[(long)c * NN + n0 + tx];
    }
    __syncthreads();
    bf16* ohz = oh + (long)z * NN * Cc;
    bf16* olz = ol + (long)z * NN * Cc;
#pragma unroll
    for (int j = 0; j < 4; j++){
        int n = n0 + ty + j * 8;
        float v = tile[tx][ty + j * 8];
        bf16 h = __float2bfloat16(v);
        long idx = (long)n * Cc + c0 + tx;
        ohz[idx] = h;
        olz[idx] = __float2bfloat16(v - __bfloat162float(h));
    }
}

// maxpool (1,2,2) + transpose + split: x [B,C,T,28,28] -> xsubT hi/lo [B,M,C]
__global__ void pool_xpose_split(const float* __restrict__ x,
                                 bf16* __restrict__ oh, bf16* __restrict__ ol){
    __shared__ float tile[32][33];
    const int tx = threadIdx.x, ty = threadIdx.y;
    const int m0 = blockIdx.x * 32, c0 = blockIdx.y * 32, z = blockIdx.z;
    const int m = m0 + tx;
    const int t_ = m / 196, r = m % 196, h2 = r / 14, w2 = r % 14;
#pragma unroll
    for (int j = 0; j < 4; j++){
        int c = c0 + ty + j * 8;
        const float* p = x + ((((long)z * Cc + c) * Tt + t_) * 28 + h2 * 2) * 28 + w2 * 2;
        float v = fmaxf(fmaxf(p[0], p[1]), fmaxf(p[28], p[29]));
        tile[ty + j * 8][tx] = v;
    }
    __syncthreads();
    bf16* ohz = oh + (long)z * MM * Cc;
    bf16* olz = ol + (long)z * MM * Cc;
#pragma unroll
    for (int j = 0; j < 4; j++){
        int mw = m0 + ty + j * 8;
        float v = tile[tx][ty + j * 8];
        bf16 h = __float2bfloat16(v);
        long idx = (long)mw * Cc + c0 + tx;
        ohz[idx] = h;
        olz[idx] = __float2bfloat16(v - __bfloat162float(h));
    }
}

// row softmax over 1568 keys -> single fp16 P
__global__ void softmax_fp16(const float* __restrict__ S, __half* __restrict__ ph){
    const long row = blockIdx.x;
    const float* p = S + row * MM;
    const int t = threadIdx.x;
    float v[7];
    float lm = -3.4e38f;
#pragma unroll
    for (int it = 0; it < 7; it++){
        int idx = t + it * 256;
        v[it] = (idx < MM) ? p[idx] : -3.4e38f;
        lm = fmaxf(lm, v[it]);
    }
    __shared__ float red[256];
    red[t] = lm; __syncthreads();
    for (int s = 128; s > 0; s >>= 1){ if (t < s) red[t] = fmaxf(red[t], red[t + s]); __syncthreads(); }
    float m = red[0];
    __syncthreads();
    float ls = 0.f;
#pragma unroll
    for (int it = 0; it < 7; it++){
        int idx = t + it * 256;
        if (idx < MM){ float e = __expf(v[it] - m); v[it] = e; ls += e; }
    }
    red[t] = ls; __syncthreads();
    for (int s = 128; s > 0; s >>= 1){ if (t < s) red[t] += red[t + s]; __syncthreads(); }
    float inv = 1.f / red[0];
    __half* phr = ph + row * MM;
#pragma unroll
    for (int it = 0; it < 7; it++){
        int idx = t + it * 256;
        if (idx < MM) phr[idx] = __float2half_rn(v[it] * inv);
    }
}

__global__ void affine_kernel(const float* __restrict__ bo, const float* __restrict__ gm,
                              const float* __restrict__ bt, const float* __restrict__ mn,
                              const float* __restrict__ vr,
                              float* __restrict__ scl, float* __restrict__ off){
    int c = blockIdx.x * blockDim.x + threadIdx.x;
    if (c < Cc){
        float s = gm[c] * rsqrtf(vr[c] + EPSV);
        scl[c] = s;
        off[c] = (bo[c] - mn[c]) * s + bt[c];
    }
}

// ------------------- launch -------------------
extern "C" void kernel_launch(void* const* d_in, const int* in_sizes, int n_in,
                              void* d_out, int out_size){
    const float* x       = (const float*)d_in[0];
    const float* w_theta = (const float*)d_in[1];
    const float* b_theta = (const float*)d_in[2];
    const float* w_phi   = (const float*)d_in[3];
    const float* b_phi   = (const float*)d_in[4];
    const float* w_g     = (const float*)d_in[5];
    const float* b_g     = (const float*)d_in[6];
    const float* w_out   = (const float*)d_in[7];
    const float* b_out   = (const float*)d_in[8];
    const float* bn_gm   = (const float*)d_in[9];
    const float* bn_bt   = (const float*)d_in[10];
    const float* bn_mn   = (const float*)d_in[11];
    const float* bn_vr   = (const float*)d_in[12];
    float* out = (float*)d_out;

    bf16 *xT_h, *xT_l, *xsT_h, *xsT_l, *th_h, *th_l, *ph_h, *ph_l;
    bf16 *gg_h, *p_h, *y_h;
    bf16 *wth_h, *wth_l, *wph_h, *wph_l, *wg_h, *wg_l, *wo_h;
    float *sc, *scl, *off;
    cudaGetSymbolAddress((void**)&xT_h, g_xT_h);  cudaGetSymbolAddress((void**)&xT_l, g_xT_l);
    cudaGetSymbolAddress((void**)&xsT_h, g_xsT_h);cudaGetSymbolAddress((void**)&xsT_l, g_xsT_l);
    cudaGetSymbolAddress((void**)&th_h, g_th_h);  cudaGetSymbolAddress((void**)&th_l, g_th_l);
    cudaGetSymbolAddress((void**)&ph_h, g_ph_h);  cudaGetSymbolAddress((void**)&ph_l, g_ph_l);
    cudaGetSymbolAddress((void**)&gg_h, g_g_h);
    cudaGetSymbolAddress((void**)&sc, g_sc);
    cudaGetSymbolAddress((void**)&p_h, g_p_h);
    cudaGetSymbolAddress((void**)&y_h, g_y_h);
    cudaGetSymbolAddress((void**)&wth_h, g_wth_h);cudaGetSymbolAddress((void**)&wth_l, g_wth_l);
    cudaGetSymbolAddress((void**)&wph_h, g_wph_h);cudaGetSymbolAddress((void**)&wph_l, g_wph_l);
    cudaGetSymbolAddress((void**)&wg_h, g_wg_h);  cudaGetSymbolAddress((void**)&wg_l, g_wg_l);
    cudaGetSymbolAddress((void**)&wo_h, g_wo_h);
    cudaGetSymbolAddress((void**)&scl, g_scl);    cudaGetSymbolAddress((void**)&off, g_off);

    cudaFuncSetAttribute(mma_gemm<1,2,0,0>, cudaFuncAttributeMaxDynamicSharedMemorySize, SMEMD0);
    cudaFuncSetAttribute(mma_gemm<3,1,0,0>, cudaFuncAttributeMaxDynamicSharedMemorySize, SMEMD0);
    cudaFuncSetAttribute(mma_gemm<0,0,0,0>, cudaFuncAttributeMaxDynamicSharedMemorySize, SMEMD0);
    cudaFuncSetAttribute(mma_gemm<3,0,0,3>, cudaFuncAttributeMaxDynamicSharedMemorySize, SMEMD3);
    cudaFuncSetAttribute(mma_gemm<0,0,1,3>, cudaFuncAttributeMaxDynamicSharedMemorySize, SMEMD3);

    // launch 0
    affine_kernel<<<(Cc + 255) / 256, 256>>>(b_out, bn_gm, bn_bt, bn_mn, bn_vr, scl, off);

    // launch 1: weight splits (w_out -> fp16 single)
    wsplit4<<<dim3((Ee * Cc + 255) / 256, 4), 256>>>(
        w_theta, w_phi, w_g, w_out,
        wth_h, wth_l, wph_h, wph_l, wg_h, wg_l, wo_h);

    // launch 2
    xpose_split<<<dim3(NN / 32, Cc / 32, Bb), dim3(32, 8)>>>(x, xT_h, xT_l);

    // launch 3 (ncu capture lands here): thetaT[n,e] = sum_c xT[n,c] w_theta[e,c] + b_theta[e]
    mma_gemm<1,2,0,0><<<dim3(Ee / 128, NN / 128, Bb), 256, SMEMD0>>>(
        xT_h, xT_l, (long)NN * Cc, NN,
        wth_h, wth_l, 0L, Ee, Cc,
        nullptr, th_h, th_l, (long)NN * Ee, Ee, NN, Ee,
        b_theta, nullptr, nullptr, nullptr, 0L);

    // launch 4
    pool_xpose_split<<<dim3(MM / 32, Cc / 32, Bb), dim3(32, 8)>>>(x, xsT_h, xsT_l);

    // launch 5: phiT[m,e] = sum_c xsT[m,c] w_phi[e,c] + b_phi[e]
    mma_gemm<1,2,0,0><<<dim3(Ee / 128, (MM + 127) / 128, Bb), 256, SMEMD0>>>(
        xsT_h, xsT_l, (long)MM * Cc, MM,
        wph_h, wph_l, 0L, Ee, Cc,
        nullptr, ph_h, ph_l, (long)MM * Ee, Ee, MM, Ee,
        b_phi, nullptr, nullptr, nullptr, 0L);

    // launch 6: g[e,m] = sum_c w_g[e,c] xsT[m,c] + b_g[e]   -> fp16 single
    mma_gemm<3,1,0,0><<<dim3((MM + 127) / 128, Ee / 128, Bb), 256, SMEMD0>>>(
        wg_h, wg_l, 0L, Ee,
        xsT_h, xsT_l, (long)MM * Cc, MM, Cc,
        nullptr, gg_h, nullptr, (long)Ee * MM, MM, Ee, MM,
        b_g, nullptr, nullptr, nullptr, 0L);

    // launch 7: scores[n,m] = sum_e thetaT[n,e] phiT[m,e]
    mma_gemm<0,0,0,0><<<dim3((MM + 127) / 128, NN / 128, Bb), 256, SMEMD0>>>(
        th_h, th_l, (long)NN * Ee, NN,
        ph_h, ph_l, (long)MM * Ee, MM, Ee,
        sc, nullptr, nullptr, (long)NN * MM, MM, NN, MM,
        nullptr, nullptr, nullptr, nullptr, 0L);

    // launch 8: softmax -> single fp16 P
    softmax_fp16<<<Bb * NN, 256>>>(sc, (__half*)p_h);

    // launch 9: yT[n,e] = sum_m P[n,m] g[e,m]   (fp16 1-pass, fp16 single out)
    mma_gemm<3,0,0,3><<<dim3(Ee / 128, NN / 128, Bb), 256, SMEMD3>>>(
        p_h, nullptr, (long)NN * MM, NN,
        gg_h, nullptr, (long)Ee * MM, Ee, MM,
        nullptr, y_h, nullptr, (long)NN * Ee, Ee, NN, Ee,
        nullptr, nullptr, nullptr, nullptr, 0L);

    // launch 10: out[c,n] = BN(sum_e w_out[c,e] yT[n,e]) + x[c,n]   (fp16 1-pass)
    mma_gemm<0,0,1,3><<<dim3(NN / 128, Cc / 128, Bb), 256, SMEMD3>>>(
        wo_h, nullptr, 0L, Cc,
        y_h, nullptr, (long)NN * Ee, NN, Ee,
        out, nullptr, nullptr, (long)Cc * NN, NN, Cc, NN,
        nullptr, scl, off, x, (long)Cc * NN);
}